// round 9
// baseline (speedup 1.0000x reference)
#include <cuda_runtime.h>
#include <cuda_bf16.h>
#include <cuda_fp16.h>
#include <cstdint>

#define Nn    1024
#define NPp   1025
#define NPS   1028
#define BHb   64
#define MXm   8192

typedef __nv_bfloat16 bf16;

// ---------------- device scratch ----------------
__device__ bf16  g_xh [(size_t)MXm * 512],      g_xl [(size_t)MXm * 512];
__device__ bf16  g_wqh[(size_t)512 * 512],      g_wql[(size_t)512 * 512];
__device__ bf16  g_wkvh[(size_t)1024 * 512],    g_wkvl[(size_t)1024 * 512];
__device__ bf16  g_woh[(size_t)512 * 512],      g_wol[(size_t)512 * 512];
__device__ bf16  g_th [(size_t)1088 * 64],      g_tl [(size_t)1088 * 64];
__device__ bf16  g_qh [(size_t)BHb * Nn * 64],  g_ql [(size_t)BHb * Nn * 64];   // scaled by 0.125
__device__ bf16  g_kh [(size_t)BHb * Nn * 64],  g_kl [(size_t)BHb * Nn * 64];
__device__ bf16  g_vth[(size_t)BHb * 64 * Nn],  g_vtl[(size_t)BHb * 64 * Nn];   // [bh][d][j]
__device__ bf16  g_ch [(size_t)MXm * 512],      g_cl [(size_t)MXm * 512];
__device__ __half g_Ph[(size_t)BHb * Nn * NPS];                                  // pos dots (scaled)

// ---------------- smem geometry ----------------
#define STRB  144
#define A_HI  0u
#define A_LO  18432u
#define B_HI  36864u
#define B_LO  46080u
#define BUFB  55296u
#define SMEM_1 55296
#define SMEM_2 110592

// fused-attention smem layout
#define FQ_HI   0u
#define FQ_LO   18432u
#define FKV0    36864u
#define FKVSTR  36864u
#define FK_HI   0u
#define FK_LO   9216u
#define FV_HI   18432u
#define FV_LO   27648u
#define FREDM   110592u
#define FREDS   111616u
#define SMEM_FA 112640

#define CP16(d, s)  asm volatile("cp.async.ca.shared.global [%0], [%1], 16;" :: "r"(d), "l"(s))
#define CP_COMMIT() asm volatile("cp.async.commit_group;" ::: "memory")
#define CP_WAIT(n)  asm volatile("cp.async.wait_group %0;" :: "n"(n) : "memory")

// warp-collective 4-matrix fragment load (8x8 b16 atoms)
#define LDMX4(r0, r1, r2, r3, a) \
    asm volatile("ldmatrix.sync.aligned.m8n8.x4.shared.b16 {%0,%1,%2,%3}, [%4];" \
                 : "=r"(r0), "=r"(r1), "=r"(r2), "=r"(r3) : "r"(a))

static __device__ __forceinline__ uint32_t smem_u32(const void* p) {
    uint32_t a;
    asm("{ .reg .u64 t; cvta.to.shared.u64 t, %1; cvt.u32.u64 %0, t; }" : "=r"(a) : "l"(p));
    return a;
}
static __device__ __forceinline__ void split1(float v, bf16& h, bf16& l) {
    h = __float2bfloat16(v);
    l = __float2bfloat16(v - __bfloat162float(h));
}
static __device__ __forceinline__ void split2(float v0, float v1, uint32_t& h2, uint32_t& l2) {
    bf16 h0, l0, h1, l1;
    split1(v0, h0, l0); split1(v1, h1, l1);
    h2 = (uint32_t)__bfloat16_as_ushort(h0) | ((uint32_t)__bfloat16_as_ushort(h1) << 16);
    l2 = (uint32_t)__bfloat16_as_ushort(l0) | ((uint32_t)__bfloat16_as_ushort(l1) << 16);
}
static __device__ __forceinline__ void mma_bf16(float* d, const uint32_t* a, const uint32_t* b) {
    asm volatile("mma.sync.aligned.m16n8k16.row.col.f32.bf16.bf16.f32 "
                 "{%0,%1,%2,%3}, {%4,%5,%6,%7}, {%8,%9}, {%0,%1,%2,%3};"
                 : "+f"(d[0]), "+f"(d[1]), "+f"(d[2]), "+f"(d[3])
                 : "r"(a[0]), "r"(a[1]), "r"(a[2]), "r"(a[3]), "r"(b[0]), "r"(b[1]));
}

template <int R, int T>
static __device__ __forceinline__ void stage_cp(uint32_t sdst, const bf16* src, int lds, int t) {
    #pragma unroll
    for (int i = 0; i < R * 8 / T; i++) {
        int idx = t + i * T;
        int row = idx >> 3, ch = idx & 7;
        CP16(sdst + (uint32_t)row * STRB + (uint32_t)ch * 16,
             src + (size_t)row * lds + ch * 8);
    }
}

template <int T>
static __device__ __forceinline__ void stage_all(uint32_t sb,
                                                 const bf16* ah, const bf16* al, int ldsa,
                                                 const bf16* bh, const bf16* bl, int ldsb, int t) {
    stage_cp<128, T>(sb + A_HI, ah, ldsa, t);
    stage_cp<128, T>(sb + A_LO, al, ldsa, t);
    stage_cp<64, T> (sb + B_HI, bh, ldsb, t);
    stage_cp<64, T> (sb + B_LO, bl, ldsb, t);
    CP_COMMIT();
}

// lane-offset helpers for ldmatrix addressing
static __device__ __forceinline__ uint32_t lda_off(int lane) {
    return (uint32_t)(lane & 15) * STRB + (uint32_t)(lane & 16);
}
static __device__ __forceinline__ uint32_t ldb_off(int lane) {
    return (uint32_t)((lane & 7) + ((lane & 16) >> 1)) * STRB + (uint32_t)((lane & 8) << 1);
}

// term-major K=64 stage; warp tile 32x32 (GEMM kernels, 256 thr, 4x2 warp grid)
static __device__ __forceinline__ void compute_stage(uint32_t sb, int lane, int wy, int nx,
                                                     float acc[2][4][4]) {
    const uint32_t a_base = sb + (uint32_t)(wy * 32) * STRB + lda_off(lane);
    const uint32_t b_base = sb + (uint32_t)(nx * 32) * STRB + ldb_off(lane);
    #pragma unroll
    for (int ks = 0; ks < 4; ks++) {
        uint32_t ah[2][4], al[2][4], bh[4][2], bl[4][2];
        #pragma unroll
        for (int mi = 0; mi < 2; mi++) {
            uint32_t ad = a_base + (uint32_t)(mi * 16) * STRB + (uint32_t)(ks * 32);
            LDMX4(ah[mi][0], ah[mi][1], ah[mi][2], ah[mi][3], ad + A_HI);
            LDMX4(al[mi][0], al[mi][1], al[mi][2], al[mi][3], ad + A_LO);
        }
        #pragma unroll
        for (int p = 0; p < 2; p++) {
            uint32_t bd = b_base + (uint32_t)(p * 16) * STRB + (uint32_t)(ks * 32);
            LDMX4(bh[2 * p][0], bh[2 * p][1], bh[2 * p + 1][0], bh[2 * p + 1][1], bd + B_HI);
            LDMX4(bl[2 * p][0], bl[2 * p][1], bl[2 * p + 1][0], bl[2 * p + 1][1], bd + B_LO);
        }
        #pragma unroll
        for (int ni = 0; ni < 4; ni++)
            #pragma unroll
            for (int mi = 0; mi < 2; mi++)
                mma_bf16(acc[mi][ni], ah[mi], bh[ni]);
        #pragma unroll
        for (int ni = 0; ni < 4; ni++)
            #pragma unroll
            for (int mi = 0; mi < 2; mi++)
                mma_bf16(acc[mi][ni], ah[mi], bl[ni]);
        #pragma unroll
        for (int ni = 0; ni < 4; ni++)
            #pragma unroll
            for (int mi = 0; mi < 2; mi++)
                mma_bf16(acc[mi][ni], al[mi], bh[ni]);
    }
}

// ===========================================================================
// Prep kernels
// ===========================================================================
__global__ void pack_x_kernel(const float* __restrict__ x) {
    size_t e = ((size_t)blockIdx.x * 256 + threadIdx.x) * 4;
    float4 v = *(const float4*)(x + e);
    uint32_t h0, l0, h1, l1;
    split2(v.x, v.y, h0, l0);
    split2(v.z, v.w, h1, l1);
    *(uint2*)&g_xh[e] = make_uint2(h0, h1);
    *(uint2*)&g_xl[e] = make_uint2(l0, l1);
}

__global__ void pack_w_kernel(const float* __restrict__ Wq, const float* __restrict__ Wkv,
                              const float* __restrict__ Wo) {
    size_t e0 = ((size_t)blockIdx.x * 256 + threadIdx.x) * 4;
    #pragma unroll
    for (int cc = 0; cc < 4; cc++) {
        size_t e = e0 + cc;
        bf16 h, l;
        if (e < 262144) {
            int k = (int)(e & 511), n = (int)(e >> 9);
            split1(Wq[(size_t)k * 512 + n], h, l);
            g_wqh[e] = h; g_wql[e] = l;
        } else if (e < 786432) {
            size_t m = e - 262144;
            int k = (int)(m & 511), n = (int)(m >> 9);
            split1(Wkv[(size_t)k * 1024 + n], h, l);
            g_wkvh[m] = h; g_wkvl[m] = l;
        } else {
            size_t m = e - 786432;
            int k = (int)(m & 511), n = (int)(m >> 9);
            split1(Wo[(size_t)k * 512 + n], h, l);
            g_woh[m] = h; g_wol[m] = l;
        }
    }
}

__global__ void pack_t_kernel(const float* __restrict__ T) {
    size_t e0 = ((size_t)blockIdx.x * 256 + threadIdx.x) * 4;
    #pragma unroll
    for (int cc = 0; cc < 4; cc++) {
        size_t e = e0 + cc;
        int p = (int)(e >> 6), d = (int)(e & 63);
        bf16 h = __float2bfloat16(0.f), l = h;
        if (p < NPp) split1(T[(size_t)p * 64 + d], h, l);
        g_th[e] = h; g_tl[e] = l;
    }
}

// ===========================================================================
// GEMM 1: QKV. grid(24, 64), 256 thr, warp tile 32x32.  q scaled by 0.125.
// ===========================================================================
__global__ __launch_bounds__(256, 2) void mm_qkv() {
    extern __shared__ uint8_t smem[];
    const uint32_t sb = smem_u32(smem);
    const int t = threadIdx.x, lane = t & 31, wid = t >> 5;
    const int wy = wid >> 1, nx = wid & 1;
    const int n0 = blockIdx.x * 64, m0 = blockIdx.y * 128;

    const bf16* ah = g_xh + (size_t)m0 * 512;
    const bf16* al = g_xl + (size_t)m0 * 512;
    const bf16* bh = (n0 < 512) ? (g_wqh + (size_t)n0 * 512) : (g_wkvh + (size_t)(n0 - 512) * 512);
    const bf16* bl = (n0 < 512) ? (g_wql + (size_t)n0 * 512) : (g_wkvl + (size_t)(n0 - 512) * 512);

    float acc[2][4][4] = {};
    stage_all<256>(sb, ah, al, 512, bh, bl, 512, t);
    for (int s = 0; s < 8; s++) {
        if (s + 1 < 8) {
            stage_all<256>(sb + ((s + 1) & 1) * BUFB, ah + (s + 1) * 64, al + (s + 1) * 64, 512,
                           bh + (s + 1) * 64, bl + (s + 1) * 64, 512, t);
            CP_WAIT(1);
        } else {
            CP_WAIT(0);
        }
        __syncthreads();
        compute_stage(sb + (s & 1) * BUFB, lane, wy, nx, acc);
        __syncthreads();
    }

    const int b = m0 >> 10, i0 = m0 & 1023;
    const int region = n0 >> 9;
    const int h = (n0 >> 6) & 7;
    const int bh_idx = b * 8 + h;
    const int r = lane >> 2, cc = lane & 3;
    const float sc = (region == 0) ? 0.125f : 1.0f;

    if (region == 2) {
        #pragma unroll
        for (int mi = 0; mi < 2; mi++)
        #pragma unroll
        for (int ni = 0; ni < 4; ni++)
        #pragma unroll
        for (int g = 0; g < 2; g++) {
            int i = i0 + wy * 32 + mi * 16 + r + g * 8;
            int d = nx * 32 + ni * 8 + cc * 2;
            bf16 h0, l0, h1, l1;
            split1(acc[mi][ni][2 * g],     h0, l0);
            split1(acc[mi][ni][2 * g + 1], h1, l1);
            g_vth[((size_t)bh_idx * 64 + d)     * 1024 + i] = h0;
            g_vtl[((size_t)bh_idx * 64 + d)     * 1024 + i] = l0;
            g_vth[((size_t)bh_idx * 64 + d + 1) * 1024 + i] = h1;
            g_vtl[((size_t)bh_idx * 64 + d + 1) * 1024 + i] = l1;
        }
    } else {
        bf16* dh = (region == 0 ? g_qh : g_kh) + ((size_t)bh_idx * 1024 + i0) * 64;
        bf16* dl = (region == 0 ? g_ql : g_kl) + ((size_t)bh_idx * 1024 + i0) * 64;
        #pragma unroll
        for (int mi = 0; mi < 2; mi++)
        #pragma unroll
        for (int ni = 0; ni < 4; ni++)
        #pragma unroll
        for (int g = 0; g < 2; g++) {
            int il = wy * 32 + mi * 16 + r + g * 8;
            int d  = nx * 32 + ni * 8 + cc * 2;
            uint32_t h2, l2;
            split2(sc * acc[mi][ni][2 * g], sc * acc[mi][ni][2 * g + 1], h2, l2);
            *(uint32_t*)&dh[(size_t)il * 64 + d] = h2;
            *(uint32_t*)&dl[(size_t)il * 64 + d] = l2;
        }
    }
}

// ===========================================================================
// GEMM 2: P = q_scaled . T^T  -> fp16.  grid(17, 512), 256 thr.
// ===========================================================================
__global__ __launch_bounds__(256, 2) void mm_pos() {
    extern __shared__ uint8_t smem[];
    const uint32_t sb = smem_u32(smem);
    const int t = threadIdx.x, lane = t & 31, wid = t >> 5;
    const int wy = wid >> 1, nx = wid & 1;
    const int p0 = blockIdx.x * 64, m0 = blockIdx.y * 128;

    float acc[2][4][4] = {};
    stage_all<256>(sb, g_qh + (size_t)m0 * 64, g_ql + (size_t)m0 * 64, 64,
                   g_th + (size_t)p0 * 64, g_tl + (size_t)p0 * 64, 64, t);
    CP_WAIT(0);
    __syncthreads();
    compute_stage(sb, lane, wy, nx, acc);

    const int r = lane >> 2, cc = lane & 3;
    #pragma unroll
    for (int mi = 0; mi < 2; mi++)
    #pragma unroll
    for (int ni = 0; ni < 4; ni++)
    #pragma unroll
    for (int g = 0; g < 2; g++) {
        int m = m0 + wy * 32 + mi * 16 + r + g * 8;
        int p = p0 + nx * 32 + ni * 8 + cc * 2;
        if (p + 1 < NPp) {
            __half2 hv = __floats2half2_rn(acc[mi][ni][2 * g], acc[mi][ni][2 * g + 1]);
            *(__half2*)&g_Ph[(size_t)m * NPS + p] = hv;
        } else if (p < NPp) {
            g_Ph[(size_t)m * NPS + p] = __float2half(acc[mi][ni][2 * g]);
        }
    }
}

// ===========================================================================
// Fused attention: grid(8, 64), 256 thr.  (unchanged from R8)
// ===========================================================================
static __device__ __forceinline__ void fa_stage_kv(uint32_t kvb,
                                                   const bf16* kh, const bf16* kl,
                                                   const bf16* vh, const bf16* vl,
                                                   int j0, int t) {
    stage_cp<64, 256>(kvb + FK_HI, kh + (size_t)j0 * 64, 64, t);
    stage_cp<64, 256>(kvb + FK_LO, kl + (size_t)j0 * 64, 64, t);
    stage_cp<64, 256>(kvb + FV_HI, vh + j0, 1024, t);
    stage_cp<64, 256>(kvb + FV_LO, vl + j0, 1024, t);
    CP_COMMIT();
}

__global__ __launch_bounds__(256) void fa_kernel() {
    extern __shared__ uint8_t smem[];
    const uint32_t sb = smem_u32(smem);
    const int t = threadIdx.x, lane = t & 31, wid = t >> 5;
    const int wy = wid >> 1, wx = wid & 1;
    const int r = lane >> 2, cc = lane & 3;
    const int i0 = blockIdx.x * 128, bh = blockIdx.y;

    const bf16* qh = g_qh + ((size_t)bh * 1024 + i0) * 64;
    const bf16* ql = g_ql + ((size_t)bh * 1024 + i0) * 64;
    const bf16* kh = g_kh + (size_t)bh * 1024 * 64;
    const bf16* kl = g_kl + (size_t)bh * 1024 * 64;
    const bf16* vh = g_vth + (size_t)bh * 64 * 1024;
    const bf16* vl = g_vtl + (size_t)bh * 64 * 1024;
    const __half* Pb = g_Ph + (size_t)bh * 1024 * NPS;

    stage_cp<128, 256>(sb + FQ_HI, qh, 64, t);
    stage_cp<128, 256>(sb + FQ_LO, ql, 64, t);
    fa_stage_kv(sb + FKV0, kh, kl, vh, vl, 0, t);

    const uint32_t q_base = sb + (uint32_t)(wy * 32) * STRB + lda_off(lane);
    const uint32_t k_rel  = (uint32_t)(wx * 32) * STRB + ldb_off(lane);
    const uint32_t v_rel  = ldb_off(lane) + (uint32_t)(wx * 64);

    float m_run[2][2], l_run[2][2], oacc[2][8][4];
    #pragma unroll
    for (int mi = 0; mi < 2; mi++)
        #pragma unroll
        for (int g = 0; g < 2; g++) { m_run[mi][g] = -1e30f; l_run[mi][g] = 0.f; }
    #pragma unroll
    for (int mi = 0; mi < 2; mi++)
        #pragma unroll
        for (int dn = 0; dn < 8; dn++)
            #pragma unroll
            for (int e = 0; e < 4; e++) oacc[mi][dn][e] = 0.f;

    float* redm = (float*)(smem + FREDM);
    float* reds = (float*)(smem + FREDS);

    for (int jt = 0; jt < 16; jt++) {
        const uint32_t kvb = sb + FKV0 + (uint32_t)(jt & 1) * FKVSTR;
        CP_WAIT(0);
        __syncthreads();
        if (jt + 1 < 16)
            fa_stage_kv(sb + FKV0 + (uint32_t)((jt + 1) & 1) * FKVSTR,
                        kh, kl, vh, vl, (jt + 1) * 64, t);

        float sacc[2][4][4];
        #pragma unroll
        for (int mi = 0; mi < 2; mi++)
            #pragma unroll
            for (int ni = 0; ni < 4; ni++)
                #pragma unroll
                for (int e = 0; e < 4; e++) sacc[mi][ni][e] = 0.f;

        #pragma unroll
        for (int ks = 0; ks < 4; ks++) {
            uint32_t qah[2][4], qal[2][4], kbh[4][2], kbl[4][2];
            #pragma unroll
            for (int mi = 0; mi < 2; mi++) {
                uint32_t ad = q_base + (uint32_t)(mi * 16) * STRB + (uint32_t)(ks * 32);
                LDMX4(qah[mi][0], qah[mi][1], qah[mi][2], qah[mi][3], ad + FQ_HI);
                LDMX4(qal[mi][0], qal[mi][1], qal[mi][2], qal[mi][3], ad + FQ_LO);
            }
            #pragma unroll
            for (int p = 0; p < 2; p++) {
                uint32_t bd = kvb + k_rel + (uint32_t)(p * 16) * STRB + (uint32_t)(ks * 32);
                LDMX4(kbh[2 * p][0], kbh[2 * p][1], kbh[2 * p + 1][0], kbh[2 * p + 1][1], bd + FK_HI);
                LDMX4(kbl[2 * p][0], kbl[2 * p][1], kbl[2 * p + 1][0], kbl[2 * p + 1][1], bd + FK_LO);
            }
            #pragma unroll
            for (int ni = 0; ni < 4; ni++)
                #pragma unroll
                for (int mi = 0; mi < 2; mi++)
                    mma_bf16(sacc[mi][ni], qah[mi], kbh[ni]);
            #pragma unroll
            for (int ni = 0; ni < 4; ni++)
                #pragma unroll
                for (int mi = 0; mi < 2; mi++)
                    mma_bf16(sacc[mi][ni], qah[mi], kbl[ni]);
            #pragma unroll
            for (int ni = 0; ni < 4; ni++)
                #pragma unroll
                for (int mi = 0; mi < 2; mi++)
                    mma_bf16(sacc[mi][ni], qal[mi], kbh[ni]);
        }

        // ---- positional term ----
        const int j0 = jt * 64;
        #pragma unroll
        for (int mi = 0; mi < 2; mi++)
            #pragma unroll
            for (int ni = 0; ni < 4; ni++)
                #pragma unroll
                for (int e = 0; e < 4; e++) {
                    int i = i0 + wy * 32 + mi * 16 + (e >> 1) * 8 + r;
                    int j = j0 + wx * 32 + ni * 8 + cc * 2 + (e & 1);
                    int dd = i - j;
                    dd = max(-512, min(512, dd));
                    sacc[mi][ni][e] += __half2float(Pb[(size_t)i * NPS + dd + 512]);
                }

        // ---- row max ----
        float mrow[2][2];
        #pragma unroll
        for (int mi = 0; mi < 2; mi++)
            #pragma unroll
            for (int g = 0; g < 2; g++) {
                float m = fmaxf(sacc[mi][0][2 * g], sacc[mi][0][2 * g + 1]);
                #pragma unroll
                for (int ni = 1; ni < 4; ni++)
                    m = fmaxf(m, fmaxf(sacc[mi][ni][2 * g], sacc[mi][ni][2 * g + 1]));
                m = fmaxf(m, __shfl_xor_sync(0xffffffffu, m, 1));
                m = fmaxf(m, __shfl_xor_sync(0xffffffffu, m, 2));
                mrow[mi][g] = m;
            }
        if (cc == 0) {
            #pragma unroll
            for (int mi = 0; mi < 2; mi++)
                #pragma unroll
                for (int g = 0; g < 2; g++)
                    redm[(wy * 32 + mi * 16 + g * 8 + r) * 2 + wx] = mrow[mi][g];
        }
        __syncthreads();

        float mnew[2][2], f[2][2];
        #pragma unroll
        for (int mi = 0; mi < 2; mi++)
            #pragma unroll
            for (int g = 0; g < 2; g++) {
                int lr = wy * 32 + mi * 16 + g * 8 + r;
                float tm = fmaxf(redm[lr * 2], redm[lr * 2 + 1]);
                float mn = fmaxf(m_run[mi][g], tm);
                f[mi][g] = __expf(m_run[mi][g] - mn);
                m_run[mi][g] = mn;
                mnew[mi][g] = mn;
            }

        // ---- exp + row sum ----
        #pragma unroll
        for (int mi = 0; mi < 2; mi++)
            #pragma unroll
            for (int ni = 0; ni < 4; ni++)
                #pragma unroll
                for (int e = 0; e < 4; e++)
                    sacc[mi][ni][e] = __expf(sacc[mi][ni][e] - mnew[mi][e >> 1]);

        float srow[2][2];
        #pragma unroll
        for (int mi = 0; mi < 2; mi++)
            #pragma unroll
            for (int g = 0; g < 2; g++) {
                float s = 0.f;
                #pragma unroll
                for (int ni = 0; ni < 4; ni++)
                    s += sacc[mi][ni][2 * g] + sacc[mi][ni][2 * g + 1];
                s += __shfl_xor_sync(0xffffffffu, s, 1);
                s += __shfl_xor_sync(0xffffffffu, s, 2);
                srow[mi][g] = s;
            }
        if (cc == 0) {
            #pragma unroll
            for (int mi = 0; mi < 2; mi++)
                #pragma unroll
                for (int g = 0; g < 2; g++)
                    reds[(wy * 32 + mi * 16 + g * 8 + r) * 2 + wx] = srow[mi][g];
        }
        __syncthreads();
        #pragma unroll
        for (int mi = 0; mi < 2; mi++)
            #pragma unroll
            for (int g = 0; g < 2; g++) {
                int lr = wy * 32 + mi * 16 + g * 8 + r;
                l_run[mi][g] = l_run[mi][g] * f[mi][g] + reds[lr * 2] + reds[lr * 2 + 1];
            }

        // ---- rescale O ----
        #pragma unroll
        for (int mi = 0; mi < 2; mi++)
            #pragma unroll
            for (int dn = 0; dn < 8; dn++)
                #pragma unroll
                for (int e = 0; e < 4; e++)
                    oacc[mi][dn][e] *= f[mi][e >> 1];

        // ---- SV (C->A identity; B from V^T via ldmatrix) ----
        #pragma unroll
        for (int ks2 = 0; ks2 < 2; ks2++) {
            uint32_t vbh[8][2], vbl[8][2];
            #pragma unroll
            for (int p3 = 0; p3 < 4; p3++) {
                uint32_t vd = kvb + v_rel + (uint32_t)(p3 * 16) * STRB + (uint32_t)(ks2 * 32);
                LDMX4(vbh[2 * p3][0], vbh[2 * p3][1], vbh[2 * p3 + 1][0], vbh[2 * p3 + 1][1],
                      vd + FV_HI);
                LDMX4(vbl[2 * p3][0], vbl[2 * p3][1], vbl[2 * p3 + 1][0], vbl[2 * p3 + 1][1],
                      vd + FV_LO);
            }
            uint32_t pah[2][4], pal[2][4];
            #pragma unroll
            for (int mi = 0; mi < 2; mi++) {
                split2(sacc[mi][2 * ks2][0],     sacc[mi][2 * ks2][1],     pah[mi][0], pal[mi][0]);
                split2(sacc[mi][2 * ks2][2],     sacc[mi][2 * ks2][3],     pah[mi][1], pal[mi][1]);
                split2(sacc[mi][2 * ks2 + 1][0], sacc[mi][2 * ks2 + 1][1], pah[mi][2], pal[mi][2]);
                split2(sacc[mi][2 * ks2 + 1][2], sacc[mi][2 * ks2 + 1][3], pah[mi][3], pal[mi][3]);
            }
            #pragma unroll
            for (int mi = 0; mi < 2; mi++)
                #pragma unroll
                for (int dn = 0; dn < 8; dn++)
                    mma_bf16(oacc[mi][dn], pah[mi], vbh[dn]);
            #pragma unroll
            for (int mi = 0; mi < 2; mi++)
                #pragma unroll
                for (int dn = 0; dn < 8; dn++)
                    mma_bf16(oacc[mi][dn], pah[mi], vbl[dn]);
            #pragma unroll
            for (int mi = 0; mi < 2; mi++)
                #pragma unroll
                for (int dn = 0; dn < 8; dn++)
                    mma_bf16(oacc[mi][dn], pal[mi], vbh[dn]);
        }
    }

    // ---- cross-wx reduction of O partials via smem ----
    __syncthreads();
    float* ored = (float*)(smem + FKV0);
    if (wx == 1) {
        #pragma unroll
        for (int mi = 0; mi < 2; mi++)
        #pragma unroll
        for (int dn = 0; dn < 8; dn++)
        #pragma unroll
        for (int g = 0; g < 2; g++) {
            int lr = mi * 16 + g * 8 + r;
            int d  = dn * 8 + cc * 2;
            *(float2*)&ored[(size_t)wy * 2048 + lr * 64 + d] =
                make_float2(oacc[mi][dn][2 * g], oacc[mi][dn][2 * g + 1]);
        }
    }
    __syncthreads();

    if (wx == 0) {
        const int b = bh >> 3, hh = bh & 7;
        float inv[2][2];
        #pragma unroll
        for (int mi = 0; mi < 2; mi++)
            #pragma unroll
            for (int g = 0; g < 2; g++) inv[mi][g] = 1.0f / l_run[mi][g];

        #pragma unroll
        for (int mi = 0; mi < 2; mi++)
        #pragma unroll
        for (int dn = 0; dn < 8; dn++)
        #pragma unroll
        for (int g = 0; g < 2; g++) {
            int lr = mi * 16 + g * 8 + r;
            int d  = dn * 8 + cc * 2;
            float2 other = *(float2*)&ored[(size_t)wy * 2048 + lr * 64 + d];
            float v0 = (oacc[mi][dn][2 * g]     + other.x) * inv[mi][g];
            float v1 = (oacc[mi][dn][2 * g + 1] + other.y) * inv[mi][g];
            int gi = i0 + wy * 32 + lr;
            uint32_t h2, l2;
            split2(v0, v1, h2, l2);
            size_t off = ((size_t)(b * 1024 + gi)) * 512 + hh * 64 + d;
            *(uint32_t*)&g_ch[off] = h2;
            *(uint32_t*)&g_cl[off] = l2;
        }
    }
}

// ===========================================================================
// GEMM 5: out = ctx @ Wo + bo.  grid(8, 64), 256 thr.
// ===========================================================================
__global__ __launch_bounds__(256, 2) void mm_out(const float* __restrict__ bo,
                                                 float* __restrict__ out) {
    extern __shared__ uint8_t smem[];
    const uint32_t sb = smem_u32(smem);
    const int t = threadIdx.x, lane = t & 31, wid = t >> 5;
    const int wy = wid >> 1, nx = wid & 1;
    const int n0 = blockIdx.x * 64, m0 = blockIdx.y * 128;

    const bf16* ah = g_ch + (size_t)m0 * 512;
    const bf16* al = g_cl + (size_t)m0 * 512;
    const bf16* bhp = g_woh + (size_t)n0 * 512;
    const bf16* blp = g_wol + (size_t)n0 * 512;

    float acc[2][4][4] = {};
    stage_all<256>(sb, ah, al, 512, bhp, blp, 512, t);
    for (int s = 0; s < 8; s++) {
        if (s + 1 < 8) {
            stage_all<256>(sb + ((s + 1) & 1) * BUFB, ah + (s + 1) * 64, al + (s + 1) * 64, 512,
                           bhp + (s + 1) * 64, blp + (s + 1) * 64, 512, t);
            CP_WAIT(1);
        } else {
            CP_WAIT(0);
        }
        __syncthreads();
        compute_stage(sb + (s & 1) * BUFB, lane, wy, nx, acc);
        __syncthreads();
    }

    const int r = lane >> 2, cc = lane & 3;
    #pragma unroll
    for (int mi = 0; mi < 2; mi++)
    #pragma unroll
    for (int ni = 0; ni < 4; ni++)
    #pragma unroll
    for (int g = 0; g < 2; g++) {
        int m = m0 + wy * 32 + mi * 16 + r + g * 8;
        int n = n0 + nx * 32 + ni * 8 + cc * 2;
        float2 v;
        v.x = acc[mi][ni][2 * g]     + bo[n];
        v.y = acc[mi][ni][2 * g + 1] + bo[n + 1];
        *(float2*)&out[(size_t)m * 512 + n] = v;
    }
}

// ===========================================================================
extern "C" void kernel_launch(void* const* d_in, const int* in_sizes, int n_in,
                              void* d_out, int out_size) {
    const float* x   = (const float*)d_in[0];
    const float* Wq  = (const float*)d_in[1];
    const float* Wkv = (const float*)d_in[2];
    const float* Wo  = (const float*)d_in[3];
    const float* bo  = (const float*)d_in[4];
    const float* pos = (const float*)d_in[5];
    float* out = (float*)d_out;

    cudaFuncSetAttribute(mm_qkv,    cudaFuncAttributeMaxDynamicSharedMemorySize, SMEM_2);
    cudaFuncSetAttribute(mm_pos,    cudaFuncAttributeMaxDynamicSharedMemorySize, SMEM_1);
    cudaFuncSetAttribute(fa_kernel, cudaFuncAttributeMaxDynamicSharedMemorySize, SMEM_FA);
    cudaFuncSetAttribute(mm_out,    cudaFuncAttributeMaxDynamicSharedMemorySize, SMEM_2);

    pack_x_kernel<<<4096, 256>>>(x);
    pack_w_kernel<<<1024, 256>>>(Wq, Wkv, Wo);
    pack_t_kernel<<<68, 256>>>(pos);

    mm_qkv   <<<dim3(24, 64),  256, SMEM_2>>>();
    mm_pos   <<<dim3(17, 512), 256, SMEM_1>>>();
    fa_kernel<<<dim3(8, 64),   256, SMEM_FA>>>();
    mm_out   <<<dim3(8, 64),   256, SMEM_2>>>(bo, out);
}

// round 10
// speedup vs baseline: 1.0630x; 1.0630x over previous
#include <cuda_runtime.h>
#include <cuda_bf16.h>
#include <cuda_fp16.h>
#include <cstdint>

#define Nn    1024
#define NPp   1025
#define NPS   1028
#define BHb   64
#define MXm   8192

typedef __nv_bfloat16 bf16;

// ---------------- device scratch ----------------
__device__ bf16  g_xh [(size_t)MXm * 512],      g_xl [(size_t)MXm * 512];
__device__ bf16  g_wqh[(size_t)512 * 512],      g_wql[(size_t)512 * 512];
__device__ bf16  g_wkvh[(size_t)1024 * 512],    g_wkvl[(size_t)1024 * 512];
__device__ bf16  g_woh[(size_t)512 * 512],      g_wol[(size_t)512 * 512];
__device__ bf16  g_th [(size_t)1088 * 64];                                       // hi only (pos 1-term)
__device__ bf16  g_qh [(size_t)BHb * Nn * 64],  g_ql [(size_t)BHb * Nn * 64];   // scaled by 0.125
__device__ bf16  g_kh [(size_t)BHb * Nn * 64],  g_kl [(size_t)BHb * Nn * 64];
__device__ bf16  g_vth[(size_t)BHb * 64 * Nn],  g_vtl[(size_t)BHb * 64 * Nn];   // [bh][d][j]
__device__ bf16  g_ch [(size_t)MXm * 512],      g_cl [(size_t)MXm * 512];
__device__ __half g_Ph[(size_t)BHb * Nn * NPS];                                  // pos dots (scaled)

// ---------------- smem geometry ----------------
#define STRB  144
#define A_HI  0u
#define A_LO  18432u
#define B_HI  36864u
#define B_LO  46080u
#define BUFB  55296u
#define SMEM_2 110592

// pos kernel (single-term) smem layout
#define PB_OFF   18432u
#define SMEM_POS 27648

// fused-attention smem layout
#define FQ_HI   0u
#define FQ_LO   18432u
#define FKV0    36864u
#define FKVSTR  36864u
#define FK_HI   0u
#define FK_LO   9216u
#define FV_HI   18432u
#define FV_LO   27648u
#define FREDM   110592u
#define FREDS   111616u
#define SMEM_FA 112640

#define CP16(d, s)  asm volatile("cp.async.ca.shared.global [%0], [%1], 16;" :: "r"(d), "l"(s))
#define CP_COMMIT() asm volatile("cp.async.commit_group;" ::: "memory")
#define CP_WAIT(n)  asm volatile("cp.async.wait_group %0;" :: "n"(n) : "memory")

// warp-collective 4-matrix fragment load (8x8 b16 atoms)
#define LDMX4(r0, r1, r2, r3, a) \
    asm volatile("ldmatrix.sync.aligned.m8n8.x4.shared.b16 {%0,%1,%2,%3}, [%4];" \
                 : "=r"(r0), "=r"(r1), "=r"(r2), "=r"(r3) : "r"(a))

static __device__ __forceinline__ uint32_t smem_u32(const void* p) {
    uint32_t a;
    asm("{ .reg .u64 t; cvta.to.shared.u64 t, %1; cvt.u32.u64 %0, t; }" : "=r"(a) : "l"(p));
    return a;
}
static __device__ __forceinline__ void split1(float v, bf16& h, bf16& l) {
    h = __float2bfloat16(v);
    l = __float2bfloat16(v - __bfloat162float(h));
}
static __device__ __forceinline__ void split2(float v0, float v1, uint32_t& h2, uint32_t& l2) {
    bf16 h0, l0, h1, l1;
    split1(v0, h0, l0); split1(v1, h1, l1);
    h2 = (uint32_t)__bfloat16_as_ushort(h0) | ((uint32_t)__bfloat16_as_ushort(h1) << 16);
    l2 = (uint32_t)__bfloat16_as_ushort(l0) | ((uint32_t)__bfloat16_as_ushort(l1) << 16);
}
static __device__ __forceinline__ void mma_bf16(float* d, const uint32_t* a, const uint32_t* b) {
    asm volatile("mma.sync.aligned.m16n8k16.row.col.f32.bf16.bf16.f32 "
                 "{%0,%1,%2,%3}, {%4,%5,%6,%7}, {%8,%9}, {%0,%1,%2,%3};"
                 : "+f"(d[0]), "+f"(d[1]), "+f"(d[2]), "+f"(d[3])
                 : "r"(a[0]), "r"(a[1]), "r"(a[2]), "r"(a[3]), "r"(b[0]), "r"(b[1]));
}

template <int R, int T>
static __device__ __forceinline__ void stage_cp(uint32_t sdst, const bf16* src, int lds, int t) {
    #pragma unroll
    for (int i = 0; i < R * 8 / T; i++) {
        int idx = t + i * T;
        int row = idx >> 3, ch = idx & 7;
        CP16(sdst + (uint32_t)row * STRB + (uint32_t)ch * 16,
             src + (size_t)row * lds + ch * 8);
    }
}

template <int T>
static __device__ __forceinline__ void stage_all(uint32_t sb,
                                                 const bf16* ah, const bf16* al, int ldsa,
                                                 const bf16* bh, const bf16* bl, int ldsb, int t) {
    stage_cp<128, T>(sb + A_HI, ah, ldsa, t);
    stage_cp<128, T>(sb + A_LO, al, ldsa, t);
    stage_cp<64, T> (sb + B_HI, bh, ldsb, t);
    stage_cp<64, T> (sb + B_LO, bl, ldsb, t);
    CP_COMMIT();
}

// lane-offset helpers for ldmatrix addressing
static __device__ __forceinline__ uint32_t lda_off(int lane) {
    return (uint32_t)(lane & 15) * STRB + (uint32_t)(lane & 16);
}
static __device__ __forceinline__ uint32_t ldb_off(int lane) {
    return (uint32_t)((lane & 7) + ((lane & 16) >> 1)) * STRB + (uint32_t)((lane & 8) << 1);
}

// term-major K=64 stage; warp tile 32x32 (GEMM kernels, 256 thr, 4x2 warp grid)
static __device__ __forceinline__ void compute_stage(uint32_t sb, int lane, int wy, int nx,
                                                     float acc[2][4][4]) {
    const uint32_t a_base = sb + (uint32_t)(wy * 32) * STRB + lda_off(lane);
    const uint32_t b_base = sb + (uint32_t)(nx * 32) * STRB + ldb_off(lane);
    #pragma unroll
    for (int ks = 0; ks < 4; ks++) {
        uint32_t ah[2][4], al[2][4], bh[4][2], bl[4][2];
        #pragma unroll
        for (int mi = 0; mi < 2; mi++) {
            uint32_t ad = a_base + (uint32_t)(mi * 16) * STRB + (uint32_t)(ks * 32);
            LDMX4(ah[mi][0], ah[mi][1], ah[mi][2], ah[mi][3], ad + A_HI);
            LDMX4(al[mi][0], al[mi][1], al[mi][2], al[mi][3], ad + A_LO);
        }
        #pragma unroll
        for (int p = 0; p < 2; p++) {
            uint32_t bd = b_base + (uint32_t)(p * 16) * STRB + (uint32_t)(ks * 32);
            LDMX4(bh[2 * p][0], bh[2 * p][1], bh[2 * p + 1][0], bh[2 * p + 1][1], bd + B_HI);
            LDMX4(bl[2 * p][0], bl[2 * p][1], bl[2 * p + 1][0], bl[2 * p + 1][1], bd + B_LO);
        }
        #pragma unroll
        for (int ni = 0; ni < 4; ni++)
            #pragma unroll
            for (int mi = 0; mi < 2; mi++)
                mma_bf16(acc[mi][ni], ah[mi], bh[ni]);
        #pragma unroll
        for (int ni = 0; ni < 4; ni++)
            #pragma unroll
            for (int mi = 0; mi < 2; mi++)
                mma_bf16(acc[mi][ni], ah[mi], bl[ni]);
        #pragma unroll
        for (int ni = 0; ni < 4; ni++)
            #pragma unroll
            for (int mi = 0; mi < 2; mi++)
                mma_bf16(acc[mi][ni], al[mi], bh[ni]);
    }
}

// ===========================================================================
// Prep kernels
// ===========================================================================
__global__ void pack_x_kernel(const float* __restrict__ x) {
    size_t e = ((size_t)blockIdx.x * 256 + threadIdx.x) * 4;
    float4 v = *(const float4*)(x + e);
    uint32_t h0, l0, h1, l1;
    split2(v.x, v.y, h0, l0);
    split2(v.z, v.w, h1, l1);
    *(uint2*)&g_xh[e] = make_uint2(h0, h1);
    *(uint2*)&g_xl[e] = make_uint2(l0, l1);
}

__global__ void pack_w_kernel(const float* __restrict__ Wq, const float* __restrict__ Wkv,
                              const float* __restrict__ Wo) {
    size_t e0 = ((size_t)blockIdx.x * 256 + threadIdx.x) * 4;
    #pragma unroll
    for (int cc = 0; cc < 4; cc++) {
        size_t e = e0 + cc;
        bf16 h, l;
        if (e < 262144) {
            int k = (int)(e & 511), n = (int)(e >> 9);
            split1(Wq[(size_t)k * 512 + n], h, l);
            g_wqh[e] = h; g_wql[e] = l;
        } else if (e < 786432) {
            size_t m = e - 262144;
            int k = (int)(m & 511), n = (int)(m >> 9);
            split1(Wkv[(size_t)k * 1024 + n], h, l);
            g_wkvh[m] = h; g_wkvl[m] = l;
        } else {
            size_t m = e - 786432;
            int k = (int)(m & 511), n = (int)(m >> 9);
            split1(Wo[(size_t)k * 512 + n], h, l);
            g_woh[m] = h; g_wol[m] = l;
        }
    }
}

__global__ void pack_t_kernel(const float* __restrict__ T) {
    size_t e0 = ((size_t)blockIdx.x * 256 + threadIdx.x) * 4;
    #pragma unroll
    for (int cc = 0; cc < 4; cc++) {
        size_t e = e0 + cc;
        int p = (int)(e >> 6), d = (int)(e & 63);
        g_th[e] = __float2bfloat16((p < NPp) ? T[(size_t)p * 64 + d] : 0.f);
    }
}

// ===========================================================================
// GEMM 1: QKV. grid(24, 64), 256 thr, warp tile 32x32.  q scaled by 0.125.
// ===========================================================================
__global__ __launch_bounds__(256, 2) void mm_qkv() {
    extern __shared__ uint8_t smem[];
    const uint32_t sb = smem_u32(smem);
    const int t = threadIdx.x, lane = t & 31, wid = t >> 5;
    const int wy = wid >> 1, nx = wid & 1;
    const int n0 = blockIdx.x * 64, m0 = blockIdx.y * 128;

    const bf16* ah = g_xh + (size_t)m0 * 512;
    const bf16* al = g_xl + (size_t)m0 * 512;
    const bf16* bh = (n0 < 512) ? (g_wqh + (size_t)n0 * 512) : (g_wkvh + (size_t)(n0 - 512) * 512);
    const bf16* bl = (n0 < 512) ? (g_wql + (size_t)n0 * 512) : (g_wkvl + (size_t)(n0 - 512) * 512);

    float acc[2][4][4] = {};
    stage_all<256>(sb, ah, al, 512, bh, bl, 512, t);
    for (int s = 0; s < 8; s++) {
        if (s + 1 < 8) {
            stage_all<256>(sb + ((s + 1) & 1) * BUFB, ah + (s + 1) * 64, al + (s + 1) * 64, 512,
                           bh + (s + 1) * 64, bl + (s + 1) * 64, 512, t);
            CP_WAIT(1);
        } else {
            CP_WAIT(0);
        }
        __syncthreads();
        compute_stage(sb + (s & 1) * BUFB, lane, wy, nx, acc);
        __syncthreads();
    }

    const int b = m0 >> 10, i0 = m0 & 1023;
    const int region = n0 >> 9;
    const int h = (n0 >> 6) & 7;
    const int bh_idx = b * 8 + h;
    const int r = lane >> 2, cc = lane & 3;
    const float sc = (region == 0) ? 0.125f : 1.0f;

    if (region == 2) {
        #pragma unroll
        for (int mi = 0; mi < 2; mi++)
        #pragma unroll
        for (int ni = 0; ni < 4; ni++)
        #pragma unroll
        for (int g = 0; g < 2; g++) {
            int i = i0 + wy * 32 + mi * 16 + r + g * 8;
            int d = nx * 32 + ni * 8 + cc * 2;
            bf16 h0, l0, h1, l1;
            split1(acc[mi][ni][2 * g],     h0, l0);
            split1(acc[mi][ni][2 * g + 1], h1, l1);
            g_vth[((size_t)bh_idx * 64 + d)     * 1024 + i] = h0;
            g_vtl[((size_t)bh_idx * 64 + d)     * 1024 + i] = l0;
            g_vth[((size_t)bh_idx * 64 + d + 1) * 1024 + i] = h1;
            g_vtl[((size_t)bh_idx * 64 + d + 1) * 1024 + i] = l1;
        }
    } else {
        bf16* dh = (region == 0 ? g_qh : g_kh) + ((size_t)bh_idx * 1024 + i0) * 64;
        bf16* dl = (region == 0 ? g_ql : g_kl) + ((size_t)bh_idx * 1024 + i0) * 64;
        #pragma unroll
        for (int mi = 0; mi < 2; mi++)
        #pragma unroll
        for (int ni = 0; ni < 4; ni++)
        #pragma unroll
        for (int g = 0; g < 2; g++) {
            int il = wy * 32 + mi * 16 + r + g * 8;
            int d  = nx * 32 + ni * 8 + cc * 2;
            uint32_t h2, l2;
            split2(sc * acc[mi][ni][2 * g], sc * acc[mi][ni][2 * g + 1], h2, l2);
            *(uint32_t*)&dh[(size_t)il * 64 + d] = h2;
            *(uint32_t*)&dl[(size_t)il * 64 + d] = l2;
        }
    }
}

// ===========================================================================
// GEMM 2: P = q_hi . T_hi^T  (SINGLE-TERM bf16; pos term sigma ~0.02 so the
// 1-term error ~6e-5 abs on logits).  -> fp16.  grid(17, 512), 256 thr.
// ===========================================================================
__global__ __launch_bounds__(256) void mm_pos() {
    extern __shared__ uint8_t smem[];
    const uint32_t sb = smem_u32(smem);
    const int t = threadIdx.x, lane = t & 31, wid = t >> 5;
    const int wy = wid >> 1, nx = wid & 1;
    const int p0 = blockIdx.x * 64, m0 = blockIdx.y * 128;

    stage_cp<128, 256>(sb, g_qh + (size_t)m0 * 64, 64, t);
    stage_cp<64, 256> (sb + PB_OFF, g_th + (size_t)p0 * 64, 64, t);
    CP_COMMIT();
    CP_WAIT(0);
    __syncthreads();

    float acc[2][4][4] = {};
    const uint32_t a_base = sb + (uint32_t)(wy * 32) * STRB + lda_off(lane);
    const uint32_t b_base = sb + PB_OFF + (uint32_t)(nx * 32) * STRB + ldb_off(lane);
    #pragma unroll
    for (int ks = 0; ks < 4; ks++) {
        uint32_t ah[2][4], bh[4][2];
        #pragma unroll
        for (int mi = 0; mi < 2; mi++) {
            uint32_t ad = a_base + (uint32_t)(mi * 16) * STRB + (uint32_t)(ks * 32);
            LDMX4(ah[mi][0], ah[mi][1], ah[mi][2], ah[mi][3], ad);
        }
        #pragma unroll
        for (int p = 0; p < 2; p++) {
            uint32_t bd = b_base + (uint32_t)(p * 16) * STRB + (uint32_t)(ks * 32);
            LDMX4(bh[2 * p][0], bh[2 * p][1], bh[2 * p + 1][0], bh[2 * p + 1][1], bd);
        }
        #pragma unroll
        for (int ni = 0; ni < 4; ni++)
            #pragma unroll
            for (int mi = 0; mi < 2; mi++)
                mma_bf16(acc[mi][ni], ah[mi], bh[ni]);
    }

    const int r = lane >> 2, cc = lane & 3;
    #pragma unroll
    for (int mi = 0; mi < 2; mi++)
    #pragma unroll
    for (int ni = 0; ni < 4; ni++)
    #pragma unroll
    for (int g = 0; g < 2; g++) {
        int m = m0 + wy * 32 + mi * 16 + r + g * 8;
        int p = p0 + nx * 32 + ni * 8 + cc * 2;
        if (p + 1 < NPp) {
            __half2 hv = __floats2half2_rn(acc[mi][ni][2 * g], acc[mi][ni][2 * g + 1]);
            *(__half2*)&g_Ph[(size_t)m * NPS + p] = hv;
        } else if (p < NPp) {
            g_Ph[(size_t)m * NPS + p] = __float2half(acc[mi][ni][2 * g]);
        }
    }
}

// ===========================================================================
// Fused attention: grid(8, 64), 256 thr.  (unchanged)
// ===========================================================================
static __device__ __forceinline__ void fa_stage_kv(uint32_t kvb,
                                                   const bf16* kh, const bf16* kl,
                                                   const bf16* vh, const bf16* vl,
                                                   int j0, int t) {
    stage_cp<64, 256>(kvb + FK_HI, kh + (size_t)j0 * 64, 64, t);
    stage_cp<64, 256>(kvb + FK_LO, kl + (size_t)j0 * 64, 64, t);
    stage_cp<64, 256>(kvb + FV_HI, vh + j0, 1024, t);
    stage_cp<64, 256>(kvb + FV_LO, vl + j0, 1024, t);
    CP_COMMIT();
}

__global__ __launch_bounds__(256) void fa_kernel() {
    extern __shared__ uint8_t smem[];
    const uint32_t sb = smem_u32(smem);
    const int t = threadIdx.x, lane = t & 31, wid = t >> 5;
    const int wy = wid >> 1, wx = wid & 1;
    const int r = lane >> 2, cc = lane & 3;
    const int i0 = blockIdx.x * 128, bh = blockIdx.y;

    const bf16* qh = g_qh + ((size_t)bh * 1024 + i0) * 64;
    const bf16* ql = g_ql + ((size_t)bh * 1024 + i0) * 64;
    const bf16* kh = g_kh + (size_t)bh * 1024 * 64;
    const bf16* kl = g_kl + (size_t)bh * 1024 * 64;
    const bf16* vh = g_vth + (size_t)bh * 64 * 1024;
    const bf16* vl = g_vtl + (size_t)bh * 64 * 1024;
    const __half* Pb = g_Ph + (size_t)bh * 1024 * NPS;

    stage_cp<128, 256>(sb + FQ_HI, qh, 64, t);
    stage_cp<128, 256>(sb + FQ_LO, ql, 64, t);
    fa_stage_kv(sb + FKV0, kh, kl, vh, vl, 0, t);

    const uint32_t q_base = sb + (uint32_t)(wy * 32) * STRB + lda_off(lane);
    const uint32_t k_rel  = (uint32_t)(wx * 32) * STRB + ldb_off(lane);
    const uint32_t v_rel  = ldb_off(lane) + (uint32_t)(wx * 64);

    float m_run[2][2], l_run[2][2], oacc[2][8][4];
    #pragma unroll
    for (int mi = 0; mi < 2; mi++)
        #pragma unroll
        for (int g = 0; g < 2; g++) { m_run[mi][g] = -1e30f; l_run[mi][g] = 0.f; }
    #pragma unroll
    for (int mi = 0; mi < 2; mi++)
        #pragma unroll
        for (int dn = 0; dn < 8; dn++)
            #pragma unroll
            for (int e = 0; e < 4; e++) oacc[mi][dn][e] = 0.f;

    float* redm = (float*)(smem + FREDM);
    float* reds = (float*)(smem + FREDS);

    for (int jt = 0; jt < 16; jt++) {
        const uint32_t kvb = sb + FKV0 + (uint32_t)(jt & 1) * FKVSTR;
        CP_WAIT(0);
        __syncthreads();
        if (jt + 1 < 16)
            fa_stage_kv(sb + FKV0 + (uint32_t)((jt + 1) & 1) * FKVSTR,
                        kh, kl, vh, vl, (jt + 1) * 64, t);

        float sacc[2][4][4];
        #pragma unroll
        for (int mi = 0; mi < 2; mi++)
            #pragma unroll
            for (int ni = 0; ni < 4; ni++)
                #pragma unroll
                for (int e = 0; e < 4; e++) sacc[mi][ni][e] = 0.f;

        #pragma unroll
        for (int ks = 0; ks < 4; ks++) {
            uint32_t qah[2][4], qal[2][4], kbh[4][2], kbl[4][2];
            #pragma unroll
            for (int mi = 0; mi < 2; mi++) {
                uint32_t ad = q_base + (uint32_t)(mi * 16) * STRB + (uint32_t)(ks * 32);
                LDMX4(qah[mi][0], qah[mi][1], qah[mi][2], qah[mi][3], ad + FQ_HI);
                LDMX4(qal[mi][0], qal[mi][1], qal[mi][2], qal[mi][3], ad + FQ_LO);
            }
            #pragma unroll
            for (int p = 0; p < 2; p++) {
                uint32_t bd = kvb + k_rel + (uint32_t)(p * 16) * STRB + (uint32_t)(ks * 32);
                LDMX4(kbh[2 * p][0], kbh[2 * p][1], kbh[2 * p + 1][0], kbh[2 * p + 1][1], bd + FK_HI);
                LDMX4(kbl[2 * p][0], kbl[2 * p][1], kbl[2 * p + 1][0], kbl[2 * p + 1][1], bd + FK_LO);
            }
            #pragma unroll
            for (int ni = 0; ni < 4; ni++)
                #pragma unroll
                for (int mi = 0; mi < 2; mi++)
                    mma_bf16(sacc[mi][ni], qah[mi], kbh[ni]);
            #pragma unroll
            for (int ni = 0; ni < 4; ni++)
                #pragma unroll
                for (int mi = 0; mi < 2; mi++)
                    mma_bf16(sacc[mi][ni], qah[mi], kbl[ni]);
            #pragma unroll
            for (int ni = 0; ni < 4; ni++)
                #pragma unroll
                for (int mi = 0; mi < 2; mi++)
                    mma_bf16(sacc[mi][ni], qal[mi], kbh[ni]);
        }

        // ---- positional term ----
        const int j0 = jt * 64;
        #pragma unroll
        for (int mi = 0; mi < 2; mi++)
            #pragma unroll
            for (int ni = 0; ni < 4; ni++)
                #pragma unroll
                for (int e = 0; e < 4; e++) {
                    int i = i0 + wy * 32 + mi * 16 + (e >> 1) * 8 + r;
                    int j = j0 + wx * 32 + ni * 8 + cc * 2 + (e & 1);
                    int dd = i - j;
                    dd = max(-512, min(512, dd));
                    sacc[mi][ni][e] += __half2float(Pb[(size_t)i * NPS + dd + 512]);
                }

        // ---- row max ----
        float mrow[2][2];
        #pragma unroll
        for (int mi = 0; mi < 2; mi++)
            #pragma unroll
            for (int g = 0; g < 2; g++) {
                float m = fmaxf(sacc[mi][0][2 * g], sacc[mi][0][2 * g + 1]);
                #pragma unroll
                for (int ni = 1; ni < 4; ni++)
                    m = fmaxf(m, fmaxf(sacc[mi][ni][2 * g], sacc[mi][ni][2 * g + 1]));
                m = fmaxf(m, __shfl_xor_sync(0xffffffffu, m, 1));
                m = fmaxf(m, __shfl_xor_sync(0xffffffffu, m, 2));
                mrow[mi][g] = m;
            }
        if (cc == 0) {
            #pragma unroll
            for (int mi = 0; mi < 2; mi++)
                #pragma unroll
                for (int g = 0; g < 2; g++)
                    redm[(wy * 32 + mi * 16 + g * 8 + r) * 2 + wx] = mrow[mi][g];
        }
        __syncthreads();

        float mnew[2][2], f[2][2];
        #pragma unroll
        for (int mi = 0; mi < 2; mi++)
            #pragma unroll
            for (int g = 0; g < 2; g++) {
                int lr = wy * 32 + mi * 16 + g * 8 + r;
                float tm = fmaxf(redm[lr * 2], redm[lr * 2 + 1]);
                float mn = fmaxf(m_run[mi][g], tm);
                f[mi][g] = __expf(m_run[mi][g] - mn);
                m_run[mi][g] = mn;
                mnew[mi][g] = mn;
            }

        // ---- exp + row sum ----
        #pragma unroll
        for (int mi = 0; mi < 2; mi++)
            #pragma unroll
            for (int ni = 0; ni < 4; ni++)
                #pragma unroll
                for (int e = 0; e < 4; e++)
                    sacc[mi][ni][e] = __expf(sacc[mi][ni][e] - mnew[mi][e >> 1]);

        float srow[2][2];
        #pragma unroll
        for (int mi = 0; mi < 2; mi++)
            #pragma unroll
            for (int g = 0; g < 2; g++) {
                float s = 0.f;
                #pragma unroll
                for (int ni = 0; ni < 4; ni++)
                    s += sacc[mi][ni][2 * g] + sacc[mi][ni][2 * g + 1];
                s += __shfl_xor_sync(0xffffffffu, s, 1);
                s += __shfl_xor_sync(0xffffffffu, s, 2);
                srow[mi][g] = s;
            }
        if (cc == 0) {
            #pragma unroll
            for (int mi = 0; mi < 2; mi++)
                #pragma unroll
                for (int g = 0; g < 2; g++)
                    reds[(wy * 32 + mi * 16 + g * 8 + r) * 2 + wx] = srow[mi][g];
        }
        __syncthreads();
        #pragma unroll
        for (int mi = 0; mi < 2; mi++)
            #pragma unroll
            for (int g = 0; g < 2; g++) {
                int lr = wy * 32 + mi * 16 + g * 8 + r;
                l_run[mi][g] = l_run[mi][g] * f[mi][g] + reds[lr * 2] + reds[lr * 2 + 1];
            }

        // ---- rescale O ----
        #pragma unroll
        for (int mi = 0; mi < 2; mi++)
            #pragma unroll
            for (int dn = 0; dn < 8; dn++)
                #pragma unroll
                for (int e = 0; e < 4; e++)
                    oacc[mi][dn][e] *= f[mi][e >> 1];

        // ---- SV (C->A identity; B from V^T via ldmatrix) ----
        #pragma unroll
        for (int ks2 = 0; ks2 < 2; ks2++) {
            uint32_t vbh[8][2], vbl[8][2];
            #pragma unroll
            for (int p3 = 0; p3 < 4; p3++) {
                uint32_t vd = kvb + v_rel + (uint32_t)(p3 * 16) * STRB + (uint32_t)(ks2 * 32);
                LDMX4(vbh[2 * p3][0], vbh[2 * p3][1], vbh[2 * p3 + 1][0], vbh[2 * p3 + 1][1],
                      vd + FV_HI);
                LDMX4(vbl[2 * p3][0], vbl[2 * p3][1], vbl[2 * p3 + 1][0], vbl[2 * p3 + 1][1],
                      vd + FV_LO);
            }
            uint32_t pah[2][4], pal[2][4];
            #pragma unroll
            for (int mi = 0; mi < 2; mi++) {
                split2(sacc[mi][2 * ks2][0],     sacc[mi][2 * ks2][1],     pah[mi][0], pal[mi][0]);
                split2(sacc[mi][2 * ks2][2],     sacc[mi][2 * ks2][3],     pah[mi][1], pal[mi][1]);
                split2(sacc[mi][2 * ks2 + 1][0], sacc[mi][2 * ks2 + 1][1], pah[mi][2], pal[mi][2]);
                split2(sacc[mi][2 * ks2 + 1][2], sacc[mi][2 * ks2 + 1][3], pah[mi][3], pal[mi][3]);
            }
            #pragma unroll
            for (int mi = 0; mi < 2; mi++)
                #pragma unroll
                for (int dn = 0; dn < 8; dn++)
                    mma_bf16(oacc[mi][dn], pah[mi], vbh[dn]);
            #pragma unroll
            for (int mi = 0; mi < 2; mi++)
                #pragma unroll
                for (int dn = 0; dn < 8; dn++)
                    mma_bf16(oacc[mi][dn], pah[mi], vbl[dn]);
            #pragma unroll
            for (int mi = 0; mi < 2; mi++)
                #pragma unroll
                for (int dn = 0; dn < 8; dn++)
                    mma_bf16(oacc[mi][dn], pal[mi], vbh[dn]);
        }
    }

    // ---- cross-wx reduction of O partials via smem ----
    __syncthreads();
    float* ored = (float*)(smem + FKV0);
    if (wx == 1) {
        #pragma unroll
        for (int mi = 0; mi < 2; mi++)
        #pragma unroll
        for (int dn = 0; dn < 8; dn++)
        #pragma unroll
        for (int g = 0; g < 2; g++) {
            int lr = mi * 16 + g * 8 + r;
            int d  = dn * 8 + cc * 2;
            *(float2*)&ored[(size_t)wy * 2048 + lr * 64 + d] =
                make_float2(oacc[mi][dn][2 * g], oacc[mi][dn][2 * g + 1]);
        }
    }
    __syncthreads();

    if (wx == 0) {
        const int b = bh >> 3, hh = bh & 7;
        float inv[2][2];
        #pragma unroll
        for (int mi = 0; mi < 2; mi++)
            #pragma unroll
            for (int g = 0; g < 2; g++) inv[mi][g] = 1.0f / l_run[mi][g];

        #pragma unroll
        for (int mi = 0; mi < 2; mi++)
        #pragma unroll
        for (int dn = 0; dn < 8; dn++)
        #pragma unroll
        for (int g = 0; g < 2; g++) {
            int lr = mi * 16 + g * 8 + r;
            int d  = dn * 8 + cc * 2;
            float2 other = *(float2*)&ored[(size_t)wy * 2048 + lr * 64 + d];
            float v0 = (oacc[mi][dn][2 * g]     + other.x) * inv[mi][g];
            float v1 = (oacc[mi][dn][2 * g + 1] + other.y) * inv[mi][g];
            int gi = i0 + wy * 32 + lr;
            uint32_t h2, l2;
            split2(v0, v1, h2, l2);
            size_t off = ((size_t)(b * 1024 + gi)) * 512 + hh * 64 + d;
            *(uint32_t*)&g_ch[off] = h2;
            *(uint32_t*)&g_cl[off] = l2;
        }
    }
}

// ===========================================================================
// GEMM 5: out = ctx @ Wo + bo.  grid(8, 64), 256 thr.
// ===========================================================================
__global__ __launch_bounds__(256, 2) void mm_out(const float* __restrict__ bo,
                                                 float* __restrict__ out) {
    extern __shared__ uint8_t smem[];
    const uint32_t sb = smem_u32(smem);
    const int t = threadIdx.x, lane = t & 31, wid = t >> 5;
    const int wy = wid >> 1, nx = wid & 1;
    const int n0 = blockIdx.x * 64, m0 = blockIdx.y * 128;

    const bf16* ah = g_ch + (size_t)m0 * 512;
    const bf16* al = g_cl + (size_t)m0 * 512;
    const bf16* bhp = g_woh + (size_t)n0 * 512;
    const bf16* blp = g_wol + (size_t)n0 * 512;

    float acc[2][4][4] = {};
    stage_all<256>(sb, ah, al, 512, bhp, blp, 512, t);
    for (int s = 0; s < 8; s++) {
        if (s + 1 < 8) {
            stage_all<256>(sb + ((s + 1) & 1) * BUFB, ah + (s + 1) * 64, al + (s + 1) * 64, 512,
                           bhp + (s + 1) * 64, blp + (s + 1) * 64, 512, t);
            CP_WAIT(1);
        } else {
            CP_WAIT(0);
        }
        __syncthreads();
        compute_stage(sb + (s & 1) * BUFB, lane, wy, nx, acc);
        __syncthreads();
    }

    const int r = lane >> 2, cc = lane & 3;
    #pragma unroll
    for (int mi = 0; mi < 2; mi++)
    #pragma unroll
    for (int ni = 0; ni < 4; ni++)
    #pragma unroll
    for (int g = 0; g < 2; g++) {
        int m = m0 + wy * 32 + mi * 16 + r + g * 8;
        int n = n0 + nx * 32 + ni * 8 + cc * 2;
        float2 v;
        v.x = acc[mi][ni][2 * g]     + bo[n];
        v.y = acc[mi][ni][2 * g + 1] + bo[n + 1];
        *(float2*)&out[(size_t)m * 512 + n] = v;
    }
}

// ===========================================================================
extern "C" void kernel_launch(void* const* d_in, const int* in_sizes, int n_in,
                              void* d_out, int out_size) {
    const float* x   = (const float*)d_in[0];
    const float* Wq  = (const float*)d_in[1];
    const float* Wkv = (const float*)d_in[2];
    const float* Wo  = (const float*)d_in[3];
    const float* bo  = (const float*)d_in[4];
    const float* pos = (const float*)d_in[5];
    float* out = (float*)d_out;

    cudaFuncSetAttribute(mm_qkv,    cudaFuncAttributeMaxDynamicSharedMemorySize, SMEM_2);
    cudaFuncSetAttribute(mm_pos,    cudaFuncAttributeMaxDynamicSharedMemorySize, SMEM_POS);
    cudaFuncSetAttribute(fa_kernel, cudaFuncAttributeMaxDynamicSharedMemorySize, SMEM_FA);
    cudaFuncSetAttribute(mm_out,    cudaFuncAttributeMaxDynamicSharedMemorySize, SMEM_2);

    pack_x_kernel<<<4096, 256>>>(x);
    pack_w_kernel<<<1024, 256>>>(Wq, Wkv, Wo);
    pack_t_kernel<<<68, 256>>>(pos);

    mm_qkv   <<<dim3(24, 64),  256, SMEM_2>>>();
    mm_pos   <<<dim3(17, 512), 256, SMEM_POS>>>();
    fa_kernel<<<dim3(8, 64),   256, SMEM_FA>>>();
    mm_out   <<<dim3(8, 64),   256, SMEM_2>>>(bo, out);
}

// round 11
// speedup vs baseline: 1.6718x; 1.5727x over previous
#include <cuda_runtime.h>
#include <cuda_fp16.h>
#include <cstdint>

#define Nn    1024
#define NPp   1025
#define NPS   1028
#define BHb   64
#define MXm   8192

typedef __half h16;

// ---------------- device scratch (all fp16 single precision) ---------------
__device__ h16 g_xf [(size_t)MXm * 512];
__device__ h16 g_wqf[(size_t)512 * 512];        // [n][k]
__device__ h16 g_wkvf[(size_t)1024 * 512];      // [n][k]
__device__ h16 g_wof[(size_t)512 * 512];        // [n][k]
__device__ h16 g_tf [(size_t)1088 * 64];        // pos table (padded)
__device__ h16 g_qf [(size_t)BHb * Nn * 64];    // scaled by 0.125
__device__ h16 g_kf [(size_t)BHb * Nn * 64];
__device__ h16 g_vtf[(size_t)BHb * 64 * Nn];    // v^T [bh][d][j]
__device__ h16 g_cf [(size_t)MXm * 512];        // ctx [b,n][h*d]
__device__ h16 g_Ph [(size_t)BHb * Nn * NPS];   // pos dots (scaled)

// ---------------- smem geometry ----------------
#define STRB  144
// GEMM kernels: A tile 128 rows, B tile 64 rows, 2 stages
#define B_OFF  18432u
#define BUFB   27648u
#define SMEM_G 55296
// fused attention
#define FQ     0u
#define FKV0   18432u
#define FKVSTR 18432u
#define FK     0u
#define FV     9216u
#define FREDM  55296u
#define FREDS  56320u
#define SMEM_FA 57344

#define CP16(d, s)  asm volatile("cp.async.ca.shared.global [%0], [%1], 16;" :: "r"(d), "l"(s))
#define CP_COMMIT() asm volatile("cp.async.commit_group;" ::: "memory")
#define CP_WAIT(n)  asm volatile("cp.async.wait_group %0;" :: "n"(n) : "memory")

#define LDMX4(r0, r1, r2, r3, a) \
    asm volatile("ldmatrix.sync.aligned.m8n8.x4.shared.b16 {%0,%1,%2,%3}, [%4];" \
                 : "=r"(r0), "=r"(r1), "=r"(r2), "=r"(r3) : "r"(a))

static __device__ __forceinline__ uint32_t smem_u32(const void* p) {
    uint32_t a;
    asm("{ .reg .u64 t; cvta.to.shared.u64 t, %1; cvt.u32.u64 %0, t; }" : "=r"(a) : "l"(p));
    return a;
}
static __device__ __forceinline__ void mma_f16(float* d, const uint32_t* a, const uint32_t* b) {
    asm volatile("mma.sync.aligned.m16n8k16.row.col.f32.f16.f16.f32 "
                 "{%0,%1,%2,%3}, {%4,%5,%6,%7}, {%8,%9}, {%0,%1,%2,%3};"
                 : "+f"(d[0]), "+f"(d[1]), "+f"(d[2]), "+f"(d[3])
                 : "r"(a[0]), "r"(a[1]), "r"(a[2]), "r"(a[3]), "r"(b[0]), "r"(b[1]));
}
static __device__ __forceinline__ uint32_t h2u(float a, float b) {
    __half2 h = __floats2half2_rn(a, b);
    return *(uint32_t*)&h;
}

template <int R, int T>
static __device__ __forceinline__ void stage_cp(uint32_t sdst, const h16* src, int lds, int t) {
    #pragma unroll
    for (int i = 0; i < R * 8 / T; i++) {
        int idx = t + i * T;
        int row = idx >> 3, ch = idx & 7;
        CP16(sdst + (uint32_t)row * STRB + (uint32_t)ch * 16,
             src + (size_t)row * lds + ch * 8);
    }
}

// lane-offset helpers for ldmatrix addressing
static __device__ __forceinline__ uint32_t lda_off(int lane) {
    return (uint32_t)(lane & 15) * STRB + (uint32_t)(lane & 16);
}
static __device__ __forceinline__ uint32_t ldb_off(int lane) {
    return (uint32_t)((lane & 7) + ((lane & 16) >> 1)) * STRB + (uint32_t)((lane & 8) << 1);
}

// single-term K=64 stage; warp tile 32x32 (256 thr, 4x2 warp grid)
static __device__ __forceinline__ void compute_stage(uint32_t sb, int lane, int wy, int nx,
                                                     float acc[2][4][4]) {
    const uint32_t a_base = sb + (uint32_t)(wy * 32) * STRB + lda_off(lane);
    const uint32_t b_base = sb + B_OFF + (uint32_t)(nx * 32) * STRB + ldb_off(lane);
    #pragma unroll
    for (int ks = 0; ks < 4; ks++) {
        uint32_t a[2][4], b[4][2];
        #pragma unroll
        for (int mi = 0; mi < 2; mi++) {
            uint32_t ad = a_base + (uint32_t)(mi * 16) * STRB + (uint32_t)(ks * 32);
            LDMX4(a[mi][0], a[mi][1], a[mi][2], a[mi][3], ad);
        }
        #pragma unroll
        for (int p = 0; p < 2; p++) {
            uint32_t bd = b_base + (uint32_t)(p * 16) * STRB + (uint32_t)(ks * 32);
            LDMX4(b[2 * p][0], b[2 * p][1], b[2 * p + 1][0], b[2 * p + 1][1], bd);
        }
        #pragma unroll
        for (int ni = 0; ni < 4; ni++)
            #pragma unroll
            for (int mi = 0; mi < 2; mi++)
                mma_f16(acc[mi][ni], a[mi], b[ni]);
    }
}

// ===========================================================================
// Prep kernels
// ===========================================================================
__global__ void pack_x_kernel(const float* __restrict__ x) {
    size_t e = ((size_t)blockIdx.x * 256 + threadIdx.x) * 4;
    float4 v = *(const float4*)(x + e);
    uint2 p;
    p.x = h2u(v.x, v.y);
    p.y = h2u(v.z, v.w);
    *(uint2*)&g_xf[e] = p;
}

__global__ void pack_w_kernel(const float* __restrict__ Wq, const float* __restrict__ Wkv,
                              const float* __restrict__ Wo) {
    size_t e0 = ((size_t)blockIdx.x * 256 + threadIdx.x) * 4;
    #pragma unroll
    for (int cc = 0; cc < 4; cc++) {
        size_t e = e0 + cc;
        if (e < 262144) {
            int k = (int)(e & 511), n = (int)(e >> 9);
            g_wqf[e] = __float2half(Wq[(size_t)k * 512 + n]);
        } else if (e < 786432) {
            size_t m = e - 262144;
            int k = (int)(m & 511), n = (int)(m >> 9);
            g_wkvf[m] = __float2half(Wkv[(size_t)k * 1024 + n]);
        } else {
            size_t m = e - 786432;
            int k = (int)(m & 511), n = (int)(m >> 9);
            g_wof[m] = __float2half(Wo[(size_t)k * 512 + n]);
        }
    }
}

__global__ void pack_t_kernel(const float* __restrict__ T) {
    size_t e0 = ((size_t)blockIdx.x * 256 + threadIdx.x) * 4;
    #pragma unroll
    for (int cc = 0; cc < 4; cc++) {
        size_t e = e0 + cc;
        int p = (int)(e >> 6), d = (int)(e & 63);
        g_tf[e] = __float2half((p < NPp) ? T[(size_t)p * 64 + d] : 0.f);
    }
}

// ===========================================================================
// GEMM 1: QKV = x @ [Wq|Wkv].  grid(24, 64), 256 thr.  q scaled by 0.125.
// ===========================================================================
__global__ __launch_bounds__(256) void mm_qkv() {
    extern __shared__ uint8_t smem[];
    const uint32_t sb = smem_u32(smem);
    const int t = threadIdx.x, lane = t & 31, wid = t >> 5;
    const int wy = wid >> 1, nx = wid & 1;
    const int n0 = blockIdx.x * 64, m0 = blockIdx.y * 128;

    const h16* A = g_xf + (size_t)m0 * 512;
    const h16* B = (n0 < 512) ? (g_wqf + (size_t)n0 * 512) : (g_wkvf + (size_t)(n0 - 512) * 512);

    float acc[2][4][4] = {};
    stage_cp<128, 256>(sb, A, 512, t);
    stage_cp<64, 256>(sb + B_OFF, B, 512, t);
    CP_COMMIT();
    for (int s = 0; s < 8; s++) {
        if (s + 1 < 8) {
            uint32_t nb = sb + ((s + 1) & 1) * BUFB;
            stage_cp<128, 256>(nb, A + (s + 1) * 64, 512, t);
            stage_cp<64, 256>(nb + B_OFF, B + (s + 1) * 64, 512, t);
            CP_COMMIT();
            CP_WAIT(1);
        } else {
            CP_WAIT(0);
        }
        __syncthreads();
        compute_stage(sb + (s & 1) * BUFB, lane, wy, nx, acc);
        __syncthreads();
    }

    const int b = m0 >> 10, i0 = m0 & 1023;
    const int region = n0 >> 9;
    const int h = (n0 >> 6) & 7;
    const int bh_idx = b * 8 + h;
    const int r = lane >> 2, cc = lane & 3;
    const float sc = (region == 0) ? 0.125f : 1.0f;

    if (region == 2) {
        #pragma unroll
        for (int mi = 0; mi < 2; mi++)
        #pragma unroll
        for (int ni = 0; ni < 4; ni++)
        #pragma unroll
        for (int g = 0; g < 2; g++) {
            int i = i0 + wy * 32 + mi * 16 + r + g * 8;
            int d = nx * 32 + ni * 8 + cc * 2;
            g_vtf[((size_t)bh_idx * 64 + d)     * 1024 + i] = __float2half(acc[mi][ni][2 * g]);
            g_vtf[((size_t)bh_idx * 64 + d + 1) * 1024 + i] = __float2half(acc[mi][ni][2 * g + 1]);
        }
    } else {
        h16* dst = (region == 0 ? g_qf : g_kf) + ((size_t)bh_idx * 1024 + i0) * 64;
        #pragma unroll
        for (int mi = 0; mi < 2; mi++)
        #pragma unroll
        for (int ni = 0; ni < 4; ni++)
        #pragma unroll
        for (int g = 0; g < 2; g++) {
            int il = wy * 32 + mi * 16 + r + g * 8;
            int d  = nx * 32 + ni * 8 + cc * 2;
            *(uint32_t*)&dst[(size_t)il * 64 + d] =
                h2u(sc * acc[mi][ni][2 * g], sc * acc[mi][ni][2 * g + 1]);
        }
    }
}

// ===========================================================================
// GEMM 2: P = q_scaled . T^T  -> fp16.  grid(17, 512), 256 thr, single stage.
// ===========================================================================
__global__ __launch_bounds__(256) void mm_pos() {
    extern __shared__ uint8_t smem[];
    const uint32_t sb = smem_u32(smem);
    const int t = threadIdx.x, lane = t & 31, wid = t >> 5;
    const int wy = wid >> 1, nx = wid & 1;
    const int p0 = blockIdx.x * 64, m0 = blockIdx.y * 128;

    stage_cp<128, 256>(sb, g_qf + (size_t)m0 * 64, 64, t);
    stage_cp<64, 256>(sb + B_OFF, g_tf + (size_t)p0 * 64, 64, t);
    CP_COMMIT();
    CP_WAIT(0);
    __syncthreads();

    float acc[2][4][4] = {};
    compute_stage(sb, lane, wy, nx, acc);

    const int r = lane >> 2, cc = lane & 3;
    #pragma unroll
    for (int mi = 0; mi < 2; mi++)
    #pragma unroll
    for (int ni = 0; ni < 4; ni++)
    #pragma unroll
    for (int g = 0; g < 2; g++) {
        int m = m0 + wy * 32 + mi * 16 + r + g * 8;
        int p = p0 + nx * 32 + ni * 8 + cc * 2;
        if (p + 1 < NPp) {
            *(uint32_t*)&g_Ph[(size_t)m * NPS + p] = h2u(acc[mi][ni][2 * g], acc[mi][ni][2 * g + 1]);
        } else if (p < NPp) {
            g_Ph[(size_t)m * NPS + p] = __float2half(acc[mi][ni][2 * g]);
        }
    }
}

// ===========================================================================
// Fused attention: grid(8, 64), 256 thr.  fp16 single-term QK and SV.
// ===========================================================================
static __device__ __forceinline__ void fa_stage_kv(uint32_t kvb,
                                                   const h16* k, const h16* v, int j0, int t) {
    stage_cp<64, 256>(kvb + FK, k + (size_t)j0 * 64, 64, t);
    stage_cp<64, 256>(kvb + FV, v + j0, 1024, t);
    CP_COMMIT();
}

__global__ __launch_bounds__(256) void fa_kernel() {
    extern __shared__ uint8_t smem[];
    const uint32_t sb = smem_u32(smem);
    const int t = threadIdx.x, lane = t & 31, wid = t >> 5;
    const int wy = wid >> 1, wx = wid & 1;
    const int r = lane >> 2, cc = lane & 3;
    const int i0 = blockIdx.x * 128, bh = blockIdx.y;

    const h16* q = g_qf + ((size_t)bh * 1024 + i0) * 64;
    const h16* k = g_kf + (size_t)bh * 1024 * 64;
    const h16* v = g_vtf + (size_t)bh * 64 * 1024;
    const h16* Pb = g_Ph + (size_t)bh * 1024 * NPS;

    stage_cp<128, 256>(sb + FQ, q, 64, t);
    fa_stage_kv(sb + FKV0, k, v, 0, t);

    const uint32_t q_base = sb + FQ + (uint32_t)(wy * 32) * STRB + lda_off(lane);
    const uint32_t k_rel  = FK + (uint32_t)(wx * 32) * STRB + ldb_off(lane);
    const uint32_t v_rel  = FV + ldb_off(lane) + (uint32_t)(wx * 64);

    float m_run[2][2], l_run[2][2], oacc[2][8][4];
    #pragma unroll
    for (int mi = 0; mi < 2; mi++)
        #pragma unroll
        for (int g = 0; g < 2; g++) { m_run[mi][g] = -1e30f; l_run[mi][g] = 0.f; }
    #pragma unroll
    for (int mi = 0; mi < 2; mi++)
        #pragma unroll
        for (int dn = 0; dn < 8; dn++)
            #pragma unroll
            for (int e = 0; e < 4; e++) oacc[mi][dn][e] = 0.f;

    float* redm = (float*)(smem + FREDM);
    float* reds = (float*)(smem + FREDS);

    for (int jt = 0; jt < 16; jt++) {
        const uint32_t kvb = sb + FKV0 + (uint32_t)(jt & 1) * FKVSTR;
        CP_WAIT(0);
        __syncthreads();
        if (jt + 1 < 16)
            fa_stage_kv(sb + FKV0 + (uint32_t)((jt + 1) & 1) * FKVSTR, k, v, (jt + 1) * 64, t);

        // ---- QK^T (single fp16 term) ----
        float sacc[2][4][4];
        #pragma unroll
        for (int mi = 0; mi < 2; mi++)
            #pragma unroll
            for (int ni = 0; ni < 4; ni++)
                #pragma unroll
                for (int e = 0; e < 4; e++) sacc[mi][ni][e] = 0.f;

        #pragma unroll
        for (int ks = 0; ks < 4; ks++) {
            uint32_t qa[2][4], kb[4][2];
            #pragma unroll
            for (int mi = 0; mi < 2; mi++) {
                uint32_t ad = q_base + (uint32_t)(mi * 16) * STRB + (uint32_t)(ks * 32);
                LDMX4(qa[mi][0], qa[mi][1], qa[mi][2], qa[mi][3], ad);
            }
            #pragma unroll
            for (int p = 0; p < 2; p++) {
                uint32_t bd = kvb + k_rel + (uint32_t)(p * 16) * STRB + (uint32_t)(ks * 32);
                LDMX4(kb[2 * p][0], kb[2 * p][1], kb[2 * p + 1][0], kb[2 * p + 1][1], bd);
            }
            #pragma unroll
            for (int ni = 0; ni < 4; ni++)
                #pragma unroll
                for (int mi = 0; mi < 2; mi++)
                    mma_f16(sacc[mi][ni], qa[mi], kb[ni]);
        }

        // ---- positional term ----
        const int j0 = jt * 64;
        #pragma unroll
        for (int mi = 0; mi < 2; mi++)
            #pragma unroll
            for (int ni = 0; ni < 4; ni++)
                #pragma unroll
                for (int e = 0; e < 4; e++) {
                    int i = i0 + wy * 32 + mi * 16 + (e >> 1) * 8 + r;
                    int j = j0 + wx * 32 + ni * 8 + cc * 2 + (e & 1);
                    int dd = i - j;
                    dd = max(-512, min(512, dd));
                    sacc[mi][ni][e] += __half2float(Pb[(size_t)i * NPS + dd + 512]);
                }

        // ---- row max ----
        float mrow[2][2];
        #pragma unroll
        for (int mi = 0; mi < 2; mi++)
            #pragma unroll
            for (int g = 0; g < 2; g++) {
                float m = fmaxf(sacc[mi][0][2 * g], sacc[mi][0][2 * g + 1]);
                #pragma unroll
                for (int ni = 1; ni < 4; ni++)
                    m = fmaxf(m, fmaxf(sacc[mi][ni][2 * g], sacc[mi][ni][2 * g + 1]));
                m = fmaxf(m, __shfl_xor_sync(0xffffffffu, m, 1));
                m = fmaxf(m, __shfl_xor_sync(0xffffffffu, m, 2));
                mrow[mi][g] = m;
            }
        if (cc == 0) {
            #pragma unroll
            for (int mi = 0; mi < 2; mi++)
                #pragma unroll
                for (int g = 0; g < 2; g++)
                    redm[(wy * 32 + mi * 16 + g * 8 + r) * 2 + wx] = mrow[mi][g];
        }
        __syncthreads();

        float mnew[2][2], f[2][2];
        #pragma unroll
        for (int mi = 0; mi < 2; mi++)
            #pragma unroll
            for (int g = 0; g < 2; g++) {
                int lr = wy * 32 + mi * 16 + g * 8 + r;
                float tm = fmaxf(redm[lr * 2], redm[lr * 2 + 1]);
                float mn = fmaxf(m_run[mi][g], tm);
                f[mi][g] = __expf(m_run[mi][g] - mn);
                m_run[mi][g] = mn;
                mnew[mi][g] = mn;
            }

        // ---- exp + row sum ----
        #pragma unroll
        for (int mi = 0; mi < 2; mi++)
            #pragma unroll
            for (int ni = 0; ni < 4; ni++)
                #pragma unroll
                for (int e = 0; e < 4; e++)
                    sacc[mi][ni][e] = __expf(sacc[mi][ni][e] - mnew[mi][e >> 1]);

        float srow[2][2];
        #pragma unroll
        for (int mi = 0; mi < 2; mi++)
            #pragma unroll
            for (int g = 0; g < 2; g++) {
                float s = 0.f;
                #pragma unroll
                for (int ni = 0; ni < 4; ni++)
                    s += sacc[mi][ni][2 * g] + sacc[mi][ni][2 * g + 1];
                s += __shfl_xor_sync(0xffffffffu, s, 1);
                s += __shfl_xor_sync(0xffffffffu, s, 2);
                srow[mi][g] = s;
            }
        if (cc == 0) {
            #pragma unroll
            for (int mi = 0; mi < 2; mi++)
                #pragma unroll
                for (int g = 0; g < 2; g++)
                    reds[(wy * 32 + mi * 16 + g * 8 + r) * 2 + wx] = srow[mi][g];
        }
        __syncthreads();
        #pragma unroll
        for (int mi = 0; mi < 2; mi++)
            #pragma unroll
            for (int g = 0; g < 2; g++) {
                int lr = wy * 32 + mi * 16 + g * 8 + r;
                l_run[mi][g] = l_run[mi][g] * f[mi][g] + reds[lr * 2] + reds[lr * 2 + 1];
            }

        // ---- rescale O ----
        #pragma unroll
        for (int mi = 0; mi < 2; mi++)
            #pragma unroll
            for (int dn = 0; dn < 8; dn++)
                #pragma unroll
                for (int e = 0; e < 4; e++)
                    oacc[mi][dn][e] *= f[mi][e >> 1];

        // ---- SV (single fp16 term; C->A identity; B from V^T) ----
        #pragma unroll
        for (int ks2 = 0; ks2 < 2; ks2++) {
            uint32_t vb[8][2];
            #pragma unroll
            for (int p3 = 0; p3 < 4; p3++) {
                uint32_t vd = kvb + v_rel + (uint32_t)(p3 * 16) * STRB + (uint32_t)(ks2 * 32);
                LDMX4(vb[2 * p3][0], vb[2 * p3][1], vb[2 * p3 + 1][0], vb[2 * p3 + 1][1], vd);
            }
            uint32_t pa[2][4];
            #pragma unroll
            for (int mi = 0; mi < 2; mi++) {
                pa[mi][0] = h2u(sacc[mi][2 * ks2][0],     sacc[mi][2 * ks2][1]);
                pa[mi][1] = h2u(sacc[mi][2 * ks2][2],     sacc[mi][2 * ks2][3]);
                pa[mi][2] = h2u(sacc[mi][2 * ks2 + 1][0], sacc[mi][2 * ks2 + 1][1]);
                pa[mi][3] = h2u(sacc[mi][2 * ks2 + 1][2], sacc[mi][2 * ks2 + 1][3]);
            }
            #pragma unroll
            for (int mi = 0; mi < 2; mi++)
                #pragma unroll
                for (int dn = 0; dn < 8; dn++)
                    mma_f16(oacc[mi][dn], pa[mi], vb[dn]);
        }
    }

    // ---- cross-wx reduction of O partials via smem (KV region reuse) ----
    __syncthreads();
    float* ored = (float*)(smem + FKV0);   // 4 wy * 32 rows * 64 d = 32 KB
    if (wx == 1) {
        #pragma unroll
        for (int mi = 0; mi < 2; mi++)
        #pragma unroll
        for (int dn = 0; dn < 8; dn++)
        #pragma unroll
        for (int g = 0; g < 2; g++) {
            int lr = mi * 16 + g * 8 + r;
            int d  = dn * 8 + cc * 2;
            *(float2*)&ored[(size_t)wy * 2048 + lr * 64 + d] =
                make_float2(oacc[mi][dn][2 * g], oacc[mi][dn][2 * g + 1]);
        }
    }
    __syncthreads();

    if (wx == 0) {
        const int b = bh >> 3, hh = bh & 7;
        float inv[2][2];
        #pragma unroll
        for (int mi = 0; mi < 2; mi++)
            #pragma unroll
            for (int g = 0; g < 2; g++) inv[mi][g] = 1.0f / l_run[mi][g];

        #pragma unroll
        for (int mi = 0; mi < 2; mi++)
        #pragma unroll
        for (int dn = 0; dn < 8; dn++)
        #pragma unroll
        for (int g = 0; g < 2; g++) {
            int lr = mi * 16 + g * 8 + r;
            int d  = dn * 8 + cc * 2;
            float2 other = *(float2*)&ored[(size_t)wy * 2048 + lr * 64 + d];
            float v0 = (oacc[mi][dn][2 * g]     + other.x) * inv[mi][g];
            float v1 = (oacc[mi][dn][2 * g + 1] + other.y) * inv[mi][g];
            int gi = i0 + wy * 32 + lr;
            size_t off = ((size_t)(b * 1024 + gi)) * 512 + hh * 64 + d;
            *(uint32_t*)&g_cf[off] = h2u(v0, v1);
        }
    }
}

// ===========================================================================
// GEMM 5: out = ctx @ Wo + bo.  grid(8, 64), 256 thr.
// ===========================================================================
__global__ __launch_bounds__(256) void mm_out(const float* __restrict__ bo,
                                              float* __restrict__ out) {
    extern __shared__ uint8_t smem[];
    const uint32_t sb = smem_u32(smem);
    const int t = threadIdx.x, lane = t & 31, wid = t >> 5;
    const int wy = wid >> 1, nx = wid & 1;
    const int n0 = blockIdx.x * 64, m0 = blockIdx.y * 128;

    const h16* A = g_cf + (size_t)m0 * 512;
    const h16* B = g_wof + (size_t)n0 * 512;

    float acc[2][4][4] = {};
    stage_cp<128, 256>(sb, A, 512, t);
    stage_cp<64, 256>(sb + B_OFF, B, 512, t);
    CP_COMMIT();
    for (int s = 0; s < 8; s++) {
        if (s + 1 < 8) {
            uint32_t nb = sb + ((s + 1) & 1) * BUFB;
            stage_cp<128, 256>(nb, A + (s + 1) * 64, 512, t);
            stage_cp<64, 256>(nb + B_OFF, B + (s + 1) * 64, 512, t);
            CP_COMMIT();
            CP_WAIT(1);
        } else {
            CP_WAIT(0);
        }
        __syncthreads();
        compute_stage(sb + (s & 1) * BUFB, lane, wy, nx, acc);
        __syncthreads();
    }

    const int r = lane >> 2, cc = lane & 3;
    #pragma unroll
    for (int mi = 0; mi < 2; mi++)
    #pragma unroll
    for (int ni = 0; ni < 4; ni++)
    #pragma unroll
    for (int g = 0; g < 2; g++) {
        int m = m0 + wy * 32 + mi * 16 + r + g * 8;
        int n = n0 + nx * 32 + ni * 8 + cc * 2;
        float2 o;
        o.x = acc[mi][ni][2 * g]     + bo[n];
        o.y = acc[mi][ni][2 * g + 1] + bo[n + 1];
        *(float2*)&out[(size_t)m * 512 + n] = o;
    }
}

// ===========================================================================
extern "C" void kernel_launch(void* const* d_in, const int* in_sizes, int n_in,
                              void* d_out, int out_size) {
    const float* x   = (const float*)d_in[0];
    const float* Wq  = (const float*)d_in[1];
    const float* Wkv = (const float*)d_in[2];
    const float* Wo  = (const float*)d_in[3];
    const float* bo  = (const float*)d_in[4];
    const float* pos = (const float*)d_in[5];
    float* out = (float*)d_out;

    cudaFuncSetAttribute(mm_qkv,    cudaFuncAttributeMaxDynamicSharedMemorySize, SMEM_G);
    cudaFuncSetAttribute(mm_pos,    cudaFuncAttributeMaxDynamicSharedMemorySize, SMEM_G);
    cudaFuncSetAttribute(fa_kernel, cudaFuncAttributeMaxDynamicSharedMemorySize, SMEM_FA);
    cudaFuncSetAttribute(mm_out,    cudaFuncAttributeMaxDynamicSharedMemorySize, SMEM_G);

    pack_x_kernel<<<4096, 256>>>(x);
    pack_w_kernel<<<1024, 256>>>(Wq, Wkv, Wo);
    pack_t_kernel<<<68, 256>>>(pos);

    mm_qkv   <<<dim3(24, 64),  256, SMEM_G>>>();
    mm_pos   <<<dim3(17, 512), 256, SMEM_G>>>();
    fa_kernel<<<dim3(8, 64),   256, SMEM_FA>>>();
    mm_out   <<<dim3(8, 64),   256, SMEM_G>>>(bo, out);
}

// round 12
// speedup vs baseline: 1.7433x; 1.0428x over previous
#include <cuda_runtime.h>
#include <cuda_fp16.h>
#include <cstdint>

#define Nn    1024
#define NPp   1025
#define NPS   1028
#define BHb   64
#define MXm   8192

typedef __half h16;

// ---------------- device scratch (all fp16) ----------------
__device__ h16 g_xf [(size_t)MXm * 512];
__device__ h16 g_wqf[(size_t)512 * 512];        // [n][k]
__device__ h16 g_wkvf[(size_t)1024 * 512];      // [n][k]
__device__ h16 g_wof[(size_t)512 * 512];        // [n][k]
__device__ h16 g_tf [(size_t)1088 * 64];        // pos table (padded)
__device__ h16 g_qf [(size_t)BHb * Nn * 64];    // scaled by 0.125
__device__ h16 g_kf [(size_t)BHb * Nn * 64];
__device__ h16 g_vtf[(size_t)BHb * 64 * Nn];    // v^T [bh][d][j]
__device__ h16 g_cf [(size_t)MXm * 512];        // ctx [b,n][h*d]
__device__ h16 g_Ph [(size_t)BHb * Nn * NPS];   // pos dots (scaled)

// ---------------- smem geometry ----------------
#define STRB  144
// GEMM kernels (qkv/out): A 128 rows + B 64 rows, 2 stages
#define B_OFF  18432u
#define BUFB   27648u
#define SMEM_G 55296
// pos: A 128 rows persistent + 2x B 64 rows
#define PB0      18432u
#define SMEM_POS 36864
// fused attention: Q 128 rows + 2x (K 64 + V 64)
#define FQ      0u
#define FKV0    18432u
#define FKVSTR  18432u
#define FK      0u
#define FV      9216u
#define SMEM_FA 55296

#define CP16(d, s)  asm volatile("cp.async.ca.shared.global [%0], [%1], 16;" :: "r"(d), "l"(s))
#define CP_COMMIT() asm volatile("cp.async.commit_group;" ::: "memory")
#define CP_WAIT(n)  asm volatile("cp.async.wait_group %0;" :: "n"(n) : "memory")

#define LDMX4(r0, r1, r2, r3, a) \
    asm volatile("ldmatrix.sync.aligned.m8n8.x4.shared.b16 {%0,%1,%2,%3}, [%4];" \
                 : "=r"(r0), "=r"(r1), "=r"(r2), "=r"(r3) : "r"(a))

static __device__ __forceinline__ uint32_t smem_u32(const void* p) {
    uint32_t a;
    asm("{ .reg .u64 t; cvta.to.shared.u64 t, %1; cvt.u32.u64 %0, t; }" : "=r"(a) : "l"(p));
    return a;
}
static __device__ __forceinline__ void mma_f16(float* d, const uint32_t* a, const uint32_t* b) {
    asm volatile("mma.sync.aligned.m16n8k16.row.col.f32.f16.f16.f32 "
                 "{%0,%1,%2,%3}, {%4,%5,%6,%7}, {%8,%9}, {%0,%1,%2,%3};"
                 : "+f"(d[0]), "+f"(d[1]), "+f"(d[2]), "+f"(d[3])
                 : "r"(a[0]), "r"(a[1]), "r"(a[2]), "r"(a[3]), "r"(b[0]), "r"(b[1]));
}
static __device__ __forceinline__ uint32_t h2u(float a, float b) {
    __half2 h = __floats2half2_rn(a, b);
    return *(uint32_t*)&h;
}

template <int R, int T>
static __device__ __forceinline__ void stage_cp(uint32_t sdst, const h16* src, int lds, int t) {
    #pragma unroll
    for (int i = 0; i < R * 8 / T; i++) {
        int idx = t + i * T;
        int row = idx >> 3, ch = idx & 7;
        CP16(sdst + (uint32_t)row * STRB + (uint32_t)ch * 16,
             src + (size_t)row * lds + ch * 8);
    }
}

// lane-offset helpers for ldmatrix addressing
static __device__ __forceinline__ uint32_t lda_off(int lane) {
    return (uint32_t)(lane & 15) * STRB + (uint32_t)(lane & 16);
}
static __device__ __forceinline__ uint32_t ldb_off(int lane) {
    return (uint32_t)((lane & 7) + ((lane & 16) >> 1)) * STRB + (uint32_t)((lane & 8) << 1);
}

// single-term K=64 stage; warp tile 32x32; explicit A/B smem bases
static __device__ __forceinline__ void compute_stage(uint32_t a_base, uint32_t b_base,
                                                     float acc[2][4][4]) {
    #pragma unroll
    for (int ks = 0; ks < 4; ks++) {
        uint32_t a[2][4], b[4][2];
        #pragma unroll
        for (int mi = 0; mi < 2; mi++) {
            uint32_t ad = a_base + (uint32_t)(mi * 16) * STRB + (uint32_t)(ks * 32);
            LDMX4(a[mi][0], a[mi][1], a[mi][2], a[mi][3], ad);
        }
        #pragma unroll
        for (int p = 0; p < 2; p++) {
            uint32_t bd = b_base + (uint32_t)(p * 16) * STRB + (uint32_t)(ks * 32);
            LDMX4(b[2 * p][0], b[2 * p][1], b[2 * p + 1][0], b[2 * p + 1][1], bd);
        }
        #pragma unroll
        for (int ni = 0; ni < 4; ni++)
            #pragma unroll
            for (int mi = 0; mi < 2; mi++)
                mma_f16(acc[mi][ni], a[mi], b[ni]);
    }
}

// ===========================================================================
// Prep kernels
// ===========================================================================
__global__ void pack_x_kernel(const float* __restrict__ x) {
    size_t e = ((size_t)blockIdx.x * 256 + threadIdx.x) * 4;
    float4 v = *(const float4*)(x + e);
    uint2 p;
    p.x = h2u(v.x, v.y);
    p.y = h2u(v.z, v.w);
    *(uint2*)&g_xf[e] = p;
}

__global__ void pack_w_kernel(const float* __restrict__ Wq, const float* __restrict__ Wkv,
                              const float* __restrict__ Wo) {
    size_t e0 = ((size_t)blockIdx.x * 256 + threadIdx.x) * 4;
    #pragma unroll
    for (int cc = 0; cc < 4; cc++) {
        size_t e = e0 + cc;
        if (e < 262144) {
            int k = (int)(e & 511), n = (int)(e >> 9);
            g_wqf[e] = __float2half(Wq[(size_t)k * 512 + n]);
        } else if (e < 786432) {
            size_t m = e - 262144;
            int k = (int)(m & 511), n = (int)(m >> 9);
            g_wkvf[m] = __float2half(Wkv[(size_t)k * 1024 + n]);
        } else {
            size_t m = e - 786432;
            int k = (int)(m & 511), n = (int)(m >> 9);
            g_wof[m] = __float2half(Wo[(size_t)k * 512 + n]);
        }
    }
}

__global__ void pack_t_kernel(const float* __restrict__ T) {
    size_t e0 = ((size_t)blockIdx.x * 256 + threadIdx.x) * 4;
    #pragma unroll
    for (int cc = 0; cc < 4; cc++) {
        size_t e = e0 + cc;
        int p = (int)(e >> 6), d = (int)(e & 63);
        g_tf[e] = __float2half((p < NPp) ? T[(size_t)p * 64 + d] : 0.f);
    }
}

// ===========================================================================
// GEMM 1: QKV = x @ [Wq|Wkv].  grid(24, 64), 256 thr.  q scaled by 0.125.
// ===========================================================================
__global__ __launch_bounds__(256) void mm_qkv() {
    extern __shared__ uint8_t smem[];
    const uint32_t sb = smem_u32(smem);
    const int t = threadIdx.x, lane = t & 31, wid = t >> 5;
    const int wy = wid >> 1, nx = wid & 1;
    const int n0 = blockIdx.x * 64, m0 = blockIdx.y * 128;

    const h16* A = g_xf + (size_t)m0 * 512;
    const h16* B = (n0 < 512) ? (g_wqf + (size_t)n0 * 512) : (g_wkvf + (size_t)(n0 - 512) * 512);

    float acc[2][4][4] = {};
    stage_cp<128, 256>(sb, A, 512, t);
    stage_cp<64, 256>(sb + B_OFF, B, 512, t);
    CP_COMMIT();
    for (int s = 0; s < 8; s++) {
        if (s + 1 < 8) {
            uint32_t nb = sb + ((s + 1) & 1) * BUFB;
            stage_cp<128, 256>(nb, A + (s + 1) * 64, 512, t);
            stage_cp<64, 256>(nb + B_OFF, B + (s + 1) * 64, 512, t);
            CP_COMMIT();
            CP_WAIT(1);
        } else {
            CP_WAIT(0);
        }
        __syncthreads();
        uint32_t buf = sb + (s & 1) * BUFB;
        compute_stage(buf + (uint32_t)(wy * 32) * STRB + lda_off(lane),
                      buf + B_OFF + (uint32_t)(nx * 32) * STRB + ldb_off(lane), acc);
        __syncthreads();
    }

    const int b = m0 >> 10, i0 = m0 & 1023;
    const int region = n0 >> 9;
    const int h = (n0 >> 6) & 7;
    const int bh_idx = b * 8 + h;
    const int r = lane >> 2, cc = lane & 3;
    const float sc = (region == 0) ? 0.125f : 1.0f;

    if (region == 2) {
        #pragma unroll
        for (int mi = 0; mi < 2; mi++)
        #pragma unroll
        for (int ni = 0; ni < 4; ni++)
        #pragma unroll
        for (int g = 0; g < 2; g++) {
            int i = i0 + wy * 32 + mi * 16 + r + g * 8;
            int d = nx * 32 + ni * 8 + cc * 2;
            g_vtf[((size_t)bh_idx * 64 + d)     * 1024 + i] = __float2half(acc[mi][ni][2 * g]);
            g_vtf[((size_t)bh_idx * 64 + d + 1) * 1024 + i] = __float2half(acc[mi][ni][2 * g + 1]);
        }
    } else {
        h16* dst = (region == 0 ? g_qf : g_kf) + ((size_t)bh_idx * 1024 + i0) * 64;
        #pragma unroll
        for (int mi = 0; mi < 2; mi++)
        #pragma unroll
        for (int ni = 0; ni < 4; ni++)
        #pragma unroll
        for (int g = 0; g < 2; g++) {
            int il = wy * 32 + mi * 16 + r + g * 8;
            int d  = nx * 32 + ni * 8 + cc * 2;
            *(uint32_t*)&dst[(size_t)il * 64 + d] =
                h2u(sc * acc[mi][ni][2 * g], sc * acc[mi][ni][2 * g + 1]);
        }
    }
}

// ===========================================================================
// GEMM 2: P = q_scaled . T^T -> fp16.  grid(512), 256 thr.
// Persistent A (q rows staged once); loop 17 T-tiles double-buffered.
// ===========================================================================
__global__ __launch_bounds__(256) void mm_pos() {
    extern __shared__ uint8_t smem[];
    const uint32_t sb = smem_u32(smem);
    const int t = threadIdx.x, lane = t & 31, wid = t >> 5;
    const int wy = wid >> 1, nx = wid & 1;
    const int m0 = blockIdx.x * 128;
    const int r = lane >> 2, cc = lane & 3;

    stage_cp<128, 256>(sb, g_qf + (size_t)m0 * 64, 64, t);
    stage_cp<64, 256>(sb + PB0, g_tf, 64, t);
    CP_COMMIT();

    const uint32_t a_base = sb + (uint32_t)(wy * 32) * STRB + lda_off(lane);

    for (int pt = 0; pt < 17; pt++) {
        if (pt + 1 < 17) {
            stage_cp<64, 256>(sb + PB0 + ((pt + 1) & 1) * 9216u,
                              g_tf + (size_t)(pt + 1) * 64 * 64, 64, t);
            CP_COMMIT();
            CP_WAIT(1);
        } else {
            CP_WAIT(0);
        }
        __syncthreads();

        float acc[2][4][4] = {};
        uint32_t b_base = sb + PB0 + (uint32_t)(pt & 1) * 9216u
                        + (uint32_t)(nx * 32) * STRB + ldb_off(lane);
        compute_stage(a_base, b_base, acc);

        const int p0 = pt * 64;
        #pragma unroll
        for (int mi = 0; mi < 2; mi++)
        #pragma unroll
        for (int ni = 0; ni < 4; ni++)
        #pragma unroll
        for (int g = 0; g < 2; g++) {
            int m = m0 + wy * 32 + mi * 16 + r + g * 8;
            int p = p0 + nx * 32 + ni * 8 + cc * 2;
            if (p + 1 < NPp) {
                *(uint32_t*)&g_Ph[(size_t)m * NPS + p] =
                    h2u(acc[mi][ni][2 * g], acc[mi][ni][2 * g + 1]);
            } else if (p < NPp) {
                g_Ph[(size_t)m * NPS + p] = __float2half(acc[mi][ni][2 * g]);
            }
        }
        __syncthreads();
    }
}

// ===========================================================================
// Fused attention: grid(8, 64), 256 thr.  Each warp owns 16 rows x all 64 j:
// softmax fully warp-local (no cross-warp reductions, no smem stats,
// no final O reduction).  1 syncthreads per j-tile.
// ===========================================================================
static __device__ __forceinline__ void fa_stage_kv(uint32_t kvb,
                                                   const h16* k, const h16* v, int j0, int t) {
    stage_cp<64, 256>(kvb + FK, k + (size_t)j0 * 64, 64, t);
    stage_cp<64, 256>(kvb + FV, v + j0, 1024, t);
    CP_COMMIT();
}

__global__ __launch_bounds__(256) void fa_kernel() {
    extern __shared__ uint8_t smem[];
    const uint32_t sb = smem_u32(smem);
    const int t = threadIdx.x, lane = t & 31, wid = t >> 5;
    const int r = lane >> 2, cc = lane & 3;
    const int i0 = blockIdx.x * 128, bh = blockIdx.y;

    const h16* q = g_qf + ((size_t)bh * 1024 + i0) * 64;
    const h16* k = g_kf + (size_t)bh * 1024 * 64;
    const h16* v = g_vtf + (size_t)bh * 64 * 1024;
    const h16* Pb = g_Ph + (size_t)bh * 1024 * NPS;

    stage_cp<128, 256>(sb + FQ, q, 64, t);
    fa_stage_kv(sb + FKV0, k, v, 0, t);

    const uint32_t q_base = sb + FQ + (uint32_t)(wid * 16) * STRB + lda_off(lane);
    const uint32_t k_rel  = FK + ldb_off(lane);
    const uint32_t v_rel  = FV + ldb_off(lane);

    float m_run[2] = {-1e30f, -1e30f};
    float l_run[2] = {0.f, 0.f};
    float oacc[8][4] = {};

    for (int jt = 0; jt < 16; jt++) {
        const uint32_t kvb = sb + FKV0 + (uint32_t)(jt & 1) * FKVSTR;
        if (jt + 1 < 16) {
            fa_stage_kv(sb + FKV0 + (uint32_t)((jt + 1) & 1) * FKVSTR, k, v, (jt + 1) * 64, t);
            CP_WAIT(1);
        } else {
            CP_WAIT(0);
        }
        __syncthreads();

        // ---- QK^T: this warp's 16 rows x all 64 cols ----
        float sacc[8][4] = {};
        #pragma unroll
        for (int ks = 0; ks < 4; ks++) {
            uint32_t qa[4], kb[8][2];
            LDMX4(qa[0], qa[1], qa[2], qa[3], q_base + (uint32_t)(ks * 32));
            #pragma unroll
            for (int p3 = 0; p3 < 4; p3++) {
                uint32_t bd = kvb + k_rel + (uint32_t)(p3 * 16) * STRB + (uint32_t)(ks * 32);
                LDMX4(kb[2 * p3][0], kb[2 * p3][1], kb[2 * p3 + 1][0], kb[2 * p3 + 1][1], bd);
            }
            #pragma unroll
            for (int ni = 0; ni < 8; ni++)
                mma_f16(sacc[ni], qa, kb[ni]);
        }

        // ---- positional term ----
        const int j0 = jt * 64;
        #pragma unroll
        for (int ni = 0; ni < 8; ni++)
            #pragma unroll
            for (int e = 0; e < 4; e++) {
                int i = i0 + wid * 16 + (e >> 1) * 8 + r;
                int j = j0 + ni * 8 + cc * 2 + (e & 1);
                int dd = i - j;
                dd = max(-512, min(512, dd));
                sacc[ni][e] += __half2float(Pb[(size_t)i * NPS + dd + 512]);
            }

        // ---- warp-local online softmax (rows split only across cc) ----
        float mnew[2], f[2];
        #pragma unroll
        for (int g = 0; g < 2; g++) {
            float m = fmaxf(sacc[0][2 * g], sacc[0][2 * g + 1]);
            #pragma unroll
            for (int ni = 1; ni < 8; ni++)
                m = fmaxf(m, fmaxf(sacc[ni][2 * g], sacc[ni][2 * g + 1]));
            m = fmaxf(m, __shfl_xor_sync(0xffffffffu, m, 1));
            m = fmaxf(m, __shfl_xor_sync(0xffffffffu, m, 2));
            float mn = fmaxf(m_run[g], m);
            f[g] = __expf(m_run[g] - mn);
            m_run[g] = mn;
            mnew[g] = mn;
        }
        #pragma unroll
        for (int ni = 0; ni < 8; ni++)
            #pragma unroll
            for (int e = 0; e < 4; e++)
                sacc[ni][e] = __expf(sacc[ni][e] - mnew[e >> 1]);
        #pragma unroll
        for (int g = 0; g < 2; g++) {
            float s = 0.f;
            #pragma unroll
            for (int ni = 0; ni < 8; ni++)
                s += sacc[ni][2 * g] + sacc[ni][2 * g + 1];
            s += __shfl_xor_sync(0xffffffffu, s, 1);
            s += __shfl_xor_sync(0xffffffffu, s, 2);
            l_run[g] = l_run[g] * f[g] + s;
        }
        #pragma unroll
        for (int dn = 0; dn < 8; dn++)
            #pragma unroll
            for (int e = 0; e < 4; e++)
                oacc[dn][e] *= f[e >> 1];

        // ---- SV: p fragments via C->A identity; B = V^T (k chunks c=0..3) ----
        #pragma unroll
        for (int c = 0; c < 4; c++) {
            uint32_t vb[8][2];
            #pragma unroll
            for (int p3 = 0; p3 < 4; p3++) {
                uint32_t vd = kvb + v_rel + (uint32_t)(p3 * 16) * STRB + (uint32_t)(c * 32);
                LDMX4(vb[2 * p3][0], vb[2 * p3][1], vb[2 * p3 + 1][0], vb[2 * p3 + 1][1], vd);
            }
            uint32_t pa[4];
            pa[0] = h2u(sacc[2 * c][0],     sacc[2 * c][1]);
            pa[1] = h2u(sacc[2 * c][2],     sacc[2 * c][3]);
            pa[2] = h2u(sacc[2 * c + 1][0], sacc[2 * c + 1][1]);
            pa[3] = h2u(sacc[2 * c + 1][2], sacc[2 * c + 1][3]);
            #pragma unroll
            for (int dn = 0; dn < 8; dn++)
                mma_f16(oacc[dn], pa, vb[dn]);
        }
        __syncthreads();
    }

    // ---- epilogue: O /= l, write ctx fp16 (warp-local) ----
    const int b = bh >> 3, hh = bh & 7;
    float inv[2] = {1.0f / l_run[0], 1.0f / l_run[1]};
    #pragma unroll
    for (int dn = 0; dn < 8; dn++)
    #pragma unroll
    for (int g = 0; g < 2; g++) {
        int gi = i0 + wid * 16 + g * 8 + r;
        int d  = dn * 8 + cc * 2;
        size_t off = ((size_t)(b * 1024 + gi)) * 512 + hh * 64 + d;
        *(uint32_t*)&g_cf[off] = h2u(oacc[dn][2 * g] * inv[g], oacc[dn][2 * g + 1] * inv[g]);
    }
}

// ===========================================================================
// GEMM 5: out = ctx @ Wo + bo.  grid(8, 64), 256 thr.
// ===========================================================================
__global__ __launch_bounds__(256) void mm_out(const float* __restrict__ bo,
                                              float* __restrict__ out) {
    extern __shared__ uint8_t smem[];
    const uint32_t sb = smem_u32(smem);
    const int t = threadIdx.x, lane = t & 31, wid = t >> 5;
    const int wy = wid >> 1, nx = wid & 1;
    const int n0 = blockIdx.x * 64, m0 = blockIdx.y * 128;

    const h16* A = g_cf + (size_t)m0 * 512;
    const h16* B = g_wof + (size_t)n0 * 512;

    float acc[2][4][4] = {};
    stage_cp<128, 256>(sb, A, 512, t);
    stage_cp<64, 256>(sb + B_OFF, B, 512, t);
    CP_COMMIT();
    for (int s = 0; s < 8; s++) {
        if (s + 1 < 8) {
            uint32_t nb = sb + ((s + 1) & 1) * BUFB;
            stage_cp<128, 256>(nb, A + (s + 1) * 64, 512, t);
            stage_cp<64, 256>(nb + B_OFF, B + (s + 1) * 64, 512, t);
            CP_COMMIT();
            CP_WAIT(1);
        } else {
            CP_WAIT(0);
        }
        __syncthreads();
        uint32_t buf = sb + (s & 1) * BUFB;
        compute_stage(buf + (uint32_t)(wy * 32) * STRB + lda_off(lane),
                      buf + B_OFF + (uint32_t)(nx * 32) * STRB + ldb_off(lane), acc);
        __syncthreads();
    }

    const int r = lane >> 2, cc = lane & 3;
    #pragma unroll
    for (int mi = 0; mi < 2; mi++)
    #pragma unroll
    for (int ni = 0; ni < 4; ni++)
    #pragma unroll
    for (int g = 0; g < 2; g++) {
        int m = m0 + wy * 32 + mi * 16 + r + g * 8;
        int n = n0 + nx * 32 + ni * 8 + cc * 2;
        float2 o;
        o.x = acc[mi][ni][2 * g]     + bo[n];
        o.y = acc[mi][ni][2 * g + 1] + bo[n + 1];
        *(float2*)&out[(size_t)m * 512 + n] = o;
    }
}

// ===========================================================================
extern "C" void kernel_launch(void* const* d_in, const int* in_sizes, int n_in,
                              void* d_out, int out_size) {
    const float* x   = (const float*)d_in[0];
    const float* Wq  = (const float*)d_in[1];
    const float* Wkv = (const float*)d_in[2];
    const float* Wo  = (const float*)d_in[3];
    const float* bo  = (const float*)d_in[4];
    const float* pos = (const float*)d_in[5];
    float* out = (float*)d_out;

    cudaFuncSetAttribute(mm_qkv,    cudaFuncAttributeMaxDynamicSharedMemorySize, SMEM_G);
    cudaFuncSetAttribute(mm_pos,    cudaFuncAttributeMaxDynamicSharedMemorySize, SMEM_POS);
    cudaFuncSetAttribute(fa_kernel, cudaFuncAttributeMaxDynamicSharedMemorySize, SMEM_FA);
    cudaFuncSetAttribute(mm_out,    cudaFuncAttributeMaxDynamicSharedMemorySize, SMEM_G);

    pack_x_kernel<<<4096, 256>>>(x);
    pack_w_kernel<<<1024, 256>>>(Wq, Wkv, Wo);
    pack_t_kernel<<<68, 256>>>(pos);

    mm_qkv   <<<dim3(24, 64), 256, SMEM_G>>>();
    mm_pos   <<<512,          256, SMEM_POS>>>();
    fa_kernel<<<dim3(8, 64),  256, SMEM_FA>>>();
    mm_out   <<<dim3(8, 64),  256, SMEM_G>>>(bo, out);
}